// round 1
// baseline (speedup 1.0000x reference)
#include <cuda_runtime.h>
#include <math.h>

#define BB 8
#define NN 128
#define CC 128
#define C2 256
#define HH 4
#define DKK 32

__device__ float g_ep[BB*NN*NN];
__device__ float g_epattn[BB*NN*NN];
__device__ float g_Q[BB*NN*CC];
__device__ float g_K[BB*NN*CC];
__device__ float g_vp1[BB*NN*CC];
__device__ float g_vp2[BB*NN*CC];

__device__ __forceinline__ float lrelu(float x) { return x > 0.f ? x : 0.01f * x; }

#define BN_SCALE 0.9999950000374997f

// ---------------------------------------------------------------------------
// psim: one block per (b,i) row. 256 threads.
// sim tile [32j x 128c] in smem, layer1 -> h1 [32 x 256], layer2 -> h2 [32 x 129pad],
// layer3 -> e[j], then row postprocess (mask diag, topk, l1norm, renorm).
// ---------------------------------------------------------------------------
struct PsimSmem {
    float vpi[CC];        // vp[b,i,:]
    float epl[NN];        // ep_last row, diag zeroed
    float erow[NN];
    float red[NN];
    float w3s[CC];
    float sim[32 * CC];        // [j][c]
    float h1[32 * C2];         // [j][o]
    float h2[32 * (CC + 1)];   // [j][oc], padded row 129
};

__global__ void psim_kernel(const float* __restrict__ vp,
                            const float* __restrict__ ep_in,
                            float* __restrict__ ep_out,
                            const float* __restrict__ w1,
                            const float* __restrict__ w2,
                            const float* __restrict__ w3,
                            const float* __restrict__ b3,
                            int kval)
{
    extern __shared__ float smem_raw[];
    PsimSmem& s = *reinterpret_cast<PsimSmem*>(smem_raw);
    const int i = blockIdx.x;
    const int b = blockIdx.y;
    const int tid = threadIdx.x;
    const int row = b * NN + i;

    if (tid < CC) {
        s.vpi[tid] = vp[row * CC + tid];
        s.w3s[tid] = w3[tid];
        float v = ep_in[row * NN + tid];
        s.epl[tid] = (tid == i) ? 0.0f : v;
    }
    __syncthreads();

    const float b3v = b3[0];

    for (int jt = 0; jt < 4; jt++) {
        const int j0 = jt * 32;
        // --- build sim tile [32 x 128], coalesced writes ---
        for (int idx = tid; idx < 32 * CC; idx += 256) {
            int j = idx >> 7, c = idx & 127;
            float d = s.vpi[c] - vp[(b * NN + j0 + j) * CC + c];
            s.sim[idx] = d * d;
        }
        __syncthreads();

        // --- layer1: o = tid (0..255), 32 j-accumulators ---
        {
            float acc[32];
            #pragma unroll
            for (int j = 0; j < 32; j++) acc[j] = 0.f;
            const float* w1c = w1 + tid;
            #pragma unroll 2
            for (int c = 0; c < CC; c++) {
                float w = __ldg(w1c + c * C2);
                const float* sc = s.sim + c;
                #pragma unroll
                for (int j = 0; j < 32; j++) acc[j] += sc[j * CC] * w;
            }
            #pragma unroll
            for (int j = 0; j < 32; j++)
                s.h1[j * C2 + tid] = lrelu(acc[j] * BN_SCALE);
        }
        __syncthreads();

        // --- layer2: oc = tid&127, jh = tid>>7 (16 j each) ---
        {
            const int oc = tid & 127;
            const int jh = tid >> 7;
            float acc[16];
            #pragma unroll
            for (int jj = 0; jj < 16; jj++) acc[jj] = 0.f;
            const float* w2c = w2 + oc;
            #pragma unroll 2
            for (int k = 0; k < C2; k++) {
                float w = __ldg(w2c + k * CC);
                const float* hk = s.h1 + (jh * 16) * C2 + k;
                #pragma unroll
                for (int jj = 0; jj < 16; jj++) acc[jj] += hk[jj * C2] * w;
            }
            #pragma unroll
            for (int jj = 0; jj < 16; jj++)
                s.h2[(jh * 16 + jj) * (CC + 1) + oc] = lrelu(acc[jj] * BN_SCALE);
        }
        __syncthreads();

        // --- layer3 + sigmoid: one j per thread (tid<32), padded rows -> no conflicts ---
        if (tid < 32) {
            float acc = 0.f;
            #pragma unroll 4
            for (int c = 0; c < CC; c++) acc += s.h2[tid * (CC + 1) + c] * s.w3s[c];
            float x = acc + b3v;
            s.erow[j0 + tid] = 1.0f / (1.0f + expf(-x));
        }
        __syncthreads();
    }

    // --- row postprocess ---
    // ep_sum = sum(epl)
    if (tid < NN) s.red[tid] = s.epl[tid];
    __syncthreads();
    for (int st = 64; st > 0; st >>= 1) { if (tid < st) s.red[tid] += s.red[tid + st]; __syncthreads(); }
    const float epsum = s.red[0];
    __syncthreads();

    if (tid < NN) s.erow[tid] *= s.epl[tid];
    __syncthreads();

    if (kval > 0 && kval < NN) {
        int cnt = 0;
        float mine = 0.f;
        if (tid < NN) {
            mine = s.erow[tid];
            for (int jj = 0; jj < NN; jj++) {
                float v = s.erow[jj];
                cnt += (v > mine) || (v == mine && jj < tid);
            }
        }
        __syncthreads();
        if (tid < NN && cnt >= kval) s.erow[tid] = 0.f;
        __syncthreads();
    }

    // l1 sum (all nonneg)
    if (tid < NN) s.red[tid] = fabsf(s.erow[tid]);
    __syncthreads();
    for (int st = 64; st > 0; st >>= 1) { if (tid < st) s.red[tid] += s.red[tid + st]; __syncthreads(); }
    const float l1 = s.red[0];
    __syncthreads();

    const float scale = epsum / fmaxf(l1, 1e-12f);
    if (tid < NN)
        s.erow[tid] = s.erow[tid] * scale + ((tid == i) ? 1.0f : 0.0f) + 1e-6f;
    __syncthreads();

    if (tid < NN) s.red[tid] = s.erow[tid];
    __syncthreads();
    for (int st = 64; st > 0; st >>= 1) { if (tid < st) s.red[tid] += s.red[tid + st]; __syncthreads(); }
    const float rsum = s.red[0];
    __syncthreads();

    if (tid < NN) ep_out[row * NN + tid] = s.erow[tid] / rsum;
}

// ---------------------------------------------------------------------------
// Q/K projection: one block per row, thread = output channel; computes both.
// ---------------------------------------------------------------------------
__global__ void qk_kernel(const float* __restrict__ vp,
                          const float* __restrict__ wq,
                          const float* __restrict__ wk,
                          float* __restrict__ Q,
                          float* __restrict__ K)
{
    __shared__ float vr[CC];
    const int r = blockIdx.x;
    const int tid = threadIdx.x;  // 128
    vr[tid] = vp[r * CC + tid];
    __syncthreads();
    float aq = 0.f, ak = 0.f;
    #pragma unroll 4
    for (int c = 0; c < CC; c++) {
        float v = vr[c];
        aq += v * __ldg(wq + c * CC + tid);
        ak += v * __ldg(wk + c * CC + tid);
    }
    Q[r * CC + tid] = aq;
    K[r * CC + tid] = ak;
}

// ---------------------------------------------------------------------------
// MHA + ep*attn fusion: one block per (b,qi). K[b] staged padded in smem.
// ---------------------------------------------------------------------------
struct MhaSmem {
    float q[CC];
    float red[NN];
    float Ks[NN * (CC + 1)];
};

__global__ void mha_kernel(const float* __restrict__ Q,
                           const float* __restrict__ K,
                           const float* __restrict__ ep,
                           float* __restrict__ epattn)
{
    extern __shared__ float smem_raw[];
    MhaSmem& s = *reinterpret_cast<MhaSmem*>(smem_raw);
    const int qi = blockIdx.x;
    const int b = blockIdx.y;
    const int tid = threadIdx.x;  // 128
    const int row = b * NN + qi;

    s.q[tid] = Q[row * CC + tid];
    for (int idx = tid; idx < NN * CC; idx += 128) {
        int j = idx >> 7, c = idx & 127;
        s.Ks[j * (CC + 1) + c] = K[(b * NN + j) * CC + c];
    }
    __syncthreads();

    const float inv = 0.17677669529663687f;  // 1/sqrt(32)
    float acc = 0.f;
    for (int h = 0; h < HH; h++) {
        float sc = 0.f;
        const float* kr = s.Ks + tid * (CC + 1) + h * DKK;
        const float* qr = s.q + h * DKK;
        #pragma unroll
        for (int d = 0; d < DKK; d++) sc += qr[d] * kr[d];
        sc *= inv;

        s.red[tid] = sc;
        __syncthreads();
        for (int st = 64; st > 0; st >>= 1) { if (tid < st) s.red[tid] = fmaxf(s.red[tid], s.red[tid + st]); __syncthreads(); }
        float mx = s.red[0];
        __syncthreads();
        float ex = expf(sc - mx);
        s.red[tid] = ex;
        __syncthreads();
        for (int st = 64; st > 0; st >>= 1) { if (tid < st) s.red[tid] += s.red[tid + st]; __syncthreads(); }
        float sm = s.red[0];
        __syncthreads();
        acc += ex / sm;
    }
    epattn[row * NN + tid] = ep[row * NN + tid] * (acc * 0.25f);
}

// ---------------------------------------------------------------------------
// D2P: one block per (b,i). edge = l1norm(epattn row w/o diag); aggr = edge@vp;
// two-layer MLP on cat(vp, aggr).
// ---------------------------------------------------------------------------
__global__ void d2p_kernel(const float* __restrict__ epattn,
                           const float* __restrict__ vp,
                           const float* __restrict__ w1,
                           const float* __restrict__ w2,
                           float* __restrict__ vp_out)
{
    __shared__ float edge[NN];
    __shared__ float nf[2 * CC];
    __shared__ float hbuf[2 * CC];
    __shared__ float red[NN];
    const int i = blockIdx.x;
    const int b = blockIdx.y;
    const int tid = threadIdx.x;  // 128
    const int row = b * NN + i;

    float e = epattn[row * NN + tid];
    if (tid == i) e = 0.f;
    red[tid] = fabsf(e);
    __syncthreads();
    for (int st = 64; st > 0; st >>= 1) { if (tid < st) red[tid] += red[tid + st]; __syncthreads(); }
    float sE = red[0];
    __syncthreads();
    edge[tid] = e / fmaxf(sE, 1e-12f);
    nf[tid] = vp[row * CC + tid];
    __syncthreads();

    // aggr[c]: coalesced vp reads across threads
    float a = 0.f;
    #pragma unroll 4
    for (int j = 0; j < NN; j++) a += edge[j] * vp[(b * NN + j) * CC + tid];
    nf[CC + tid] = a;
    __syncthreads();

    #pragma unroll
    for (int oo = 0; oo < 2; oo++) {
        int o = tid + oo * 128;
        float acc = 0.f;
        #pragma unroll 4
        for (int k = 0; k < 2 * CC; k++) acc += nf[k] * __ldg(w1 + k * 2 * CC + o);
        hbuf[o] = lrelu(acc * BN_SCALE);
    }
    __syncthreads();

    float acc = 0.f;
    #pragma unroll 4
    for (int k = 0; k < 2 * CC; k++) acc += hbuf[k] * __ldg(w2 + k * CC + tid);
    vp_out[row * CC + tid] = lrelu(acc * BN_SCALE);
}

// ---------------------------------------------------------------------------

extern "C" void kernel_launch(void* const* d_in, const int* in_sizes, int n_in,
                              void* d_out, int out_size)
{
    const float* vp   = (const float*)d_in[0];
    const float* ep0  = (const float*)d_in[1];
    const float* pw1  = (const float*)d_in[2];
    const float* pw2  = (const float*)d_in[3];
    const float* pw3  = (const float*)d_in[4];
    const float* pb3  = (const float*)d_in[5];
    const float* psw1 = (const float*)d_in[6];
    const float* psw2 = (const float*)d_in[7];
    const float* psw3 = (const float*)d_in[8];
    const float* psb3 = (const float*)d_in[9];
    const float* dw1  = (const float*)d_in[10];
    const float* dw2  = (const float*)d_in[11];
    const float* wq   = (const float*)d_in[12];
    const float* wk   = (const float*)d_in[13];
    float* out = (float*)d_out;

    const int psim_smem = (int)sizeof(PsimSmem);
    const int mha_smem  = (int)sizeof(MhaSmem);
    cudaFuncSetAttribute(psim_kernel, cudaFuncAttributeMaxDynamicSharedMemorySize, psim_smem);
    cudaFuncSetAttribute(mha_kernel,  cudaFuncAttributeMaxDynamicSharedMemorySize, mha_smem);

    float *ep, *epattn, *Q, *K, *vp1, *vp2;
    cudaGetSymbolAddress((void**)&ep, g_ep);
    cudaGetSymbolAddress((void**)&epattn, g_epattn);
    cudaGetSymbolAddress((void**)&Q, g_Q);
    cudaGetSymbolAddress((void**)&K, g_K);
    cudaGetSymbolAddress((void**)&vp1, g_vp1);
    cudaGetSymbolAddress((void**)&vp2, g_vp2);

    dim3 grid(NN, BB);

    // pre-psim: ep0 -> g_ep (no topk)
    psim_kernel<<<grid, 256, psim_smem>>>(vp, ep0, ep, pw1, pw2, pw3, pb3, 0);

    for (int g = 0; g < 2; g++) {
        const float* vpc = (g == 0) ? vp : vp1;
        float* vpn = (g == 0) ? vp1 : vp2;

        qk_kernel<<<BB * NN, 128>>>(vpc, wq + g * CC * CC, wk + g * CC * CC, Q, K);
        mha_kernel<<<grid, 128, mha_smem>>>(Q, K, ep, epattn);
        d2p_kernel<<<grid, 128>>>(epattn, vpc,
                                  dw1 + g * 2 * CC * 2 * CC,
                                  dw2 + g * 2 * CC * CC, vpn);

        const int kv = (g == 0) ? 115 : 102;  // int(128*0.9), int(128*0.8)
        float* epo = (g == 1) ? out : ep;
        psim_kernel<<<grid, 256, psim_smem>>>(vpn, ep, epo,
                                              psw1 + g * CC * C2,
                                              psw2 + g * C2 * CC,
                                              psw3 + g * CC,
                                              psb3 + g, kv);
    }
}

// round 3
// speedup vs baseline: 1.2882x; 1.2882x over previous
#include <cuda_runtime.h>
#include <math.h>
#include <stdint.h>

#define BB 8
#define NN 128
#define CC 128
#define C2 256
#define HH 4
#define DKK 32

__device__ float g_ep[BB*NN*NN];
__device__ float g_epattn[BB*NN*NN];
__device__ float g_Q[BB*NN*CC];
__device__ float g_K[BB*NN*CC];
__device__ float g_vp1[BB*NN*CC];
__device__ float g_vp2[BB*NN*CC];

__device__ __forceinline__ float lrelu(float x) { return x > 0.f ? x : 0.01f * x; }

#define BN_SCALE 0.9999950000374997f

// ---- packed f32x2 helpers -------------------------------------------------
__device__ __forceinline__ void fma2(unsigned long long& d, unsigned long long a, unsigned long long b) {
    asm("fma.rn.f32x2 %0, %1, %2, %0;" : "+l"(d) : "l"(a), "l"(b));
}
__device__ __forceinline__ unsigned long long pack2(float lo, float hi) {
    unsigned long long d;
    asm("mov.b64 %0, {%1, %2};" : "=l"(d) : "f"(lo), "f"(hi));
    return d;
}
__device__ __forceinline__ void unpack2(unsigned long long d, float& lo, float& hi) {
    asm("mov.b64 {%0, %1}, %2;" : "=f"(lo), "=f"(hi) : "l"(d));
}
__device__ __forceinline__ void lds2(unsigned long long& a, unsigned long long& b, uint32_t addr) {
    asm("ld.shared.v2.b64 {%0, %1}, [%2];" : "=l"(a), "=l"(b) : "r"(addr));
}

// ---------------------------------------------------------------------------
// psim: one block per (b,i) row. 256 threads.
// ---------------------------------------------------------------------------
struct PsimSmem {
    float vpi[CC];
    float epl[NN];
    float erow[NN];
    float red[NN];
    float w3s[CC];
    float sim[32 * CC];        // [j][c]
    float h1[32 * C2];         // [j][o]
    float h2[32 * (CC + 1)];   // [j][oc] padded
};

__global__ void __launch_bounds__(256, 2)
psim_kernel(const float* __restrict__ vp,
            const float* __restrict__ ep_in,
            float* __restrict__ ep_out,
            const float* __restrict__ w1,
            const float* __restrict__ w2,
            const float* __restrict__ w3,
            const float* __restrict__ b3,
            int kval)
{
    extern __shared__ float smem_raw[];
    PsimSmem& s = *reinterpret_cast<PsimSmem*>(smem_raw);
    const int i = blockIdx.x;
    const int b = blockIdx.y;
    const int tid = threadIdx.x;
    const int row = b * NN + i;

    if (tid < CC) {
        s.vpi[tid] = vp[row * CC + tid];
        s.w3s[tid] = w3[tid];
        float v = ep_in[row * NN + tid];
        s.epl[tid] = (tid == i) ? 0.0f : v;
    }
    __syncthreads();

    const float b3v = b3[0];
    const uint32_t sim_b = (uint32_t)__cvta_generic_to_shared(s.sim);
    const uint32_t h1_b  = (uint32_t)__cvta_generic_to_shared(s.h1);

    for (int jt = 0; jt < 4; jt++) {
        const int j0 = jt * 32;
        // --- build sim tile [32 x 128] ---
        for (int idx = tid; idx < 32 * CC; idx += 256) {
            int j = idx >> 7, c = idx & 127;
            float d = s.vpi[c] - vp[(b * NN + j0 + j) * CC + c];
            s.sim[idx] = d * d;
        }
        __syncthreads();

        // --- layer1: o = tid, 32 packed j-accumulators ---
        {
            unsigned long long acc[32];
            #pragma unroll
            for (int j = 0; j < 32; j++) acc[j] = 0ull;
            const float* wc = w1 + tid;
            float wa = __ldg(wc);
            float wb = __ldg(wc + C2);
            float wx = __ldg(wc + 2 * C2);
            float wd = __ldg(wc + 3 * C2);
            #pragma unroll 1
            for (int c = 0; c < CC; c += 4) {
                unsigned long long wp0 = pack2(wa, wb);
                unsigned long long wp1 = pack2(wx, wd);
                int cn = (c + 4 < CC) ? (c + 4) : 0;
                wa = __ldg(wc + cn * C2);
                wb = __ldg(wc + (cn + 1) * C2);
                wx = __ldg(wc + (cn + 2) * C2);
                wd = __ldg(wc + (cn + 3) * C2);
                uint32_t base = sim_b + c * 4;
                #pragma unroll
                for (int j = 0; j < 32; j++) {
                    unsigned long long s0, s1;
                    lds2(s0, s1, base + j * (CC * 4));
                    fma2(acc[j], s0, wp0);
                    fma2(acc[j], s1, wp1);
                }
            }
            #pragma unroll
            for (int j = 0; j < 32; j++) {
                float lo, hi; unpack2(acc[j], lo, hi);
                s.h1[j * C2 + tid] = lrelu((lo + hi) * BN_SCALE);
            }
        }
        __syncthreads();

        // --- layer2: oc = tid&127, jh = tid>>7, 16 packed j-accumulators ---
        {
            const int oc = tid & 127;
            const int jh = tid >> 7;
            unsigned long long acc[16];
            #pragma unroll
            for (int jj = 0; jj < 16; jj++) acc[jj] = 0ull;
            const float* wc = w2 + oc;
            const uint32_t hb = h1_b + (jh * 16) * C2 * 4;
            float wa = __ldg(wc);
            float wb = __ldg(wc + CC);
            float wx = __ldg(wc + 2 * CC);
            float wd = __ldg(wc + 3 * CC);
            #pragma unroll 1
            for (int k = 0; k < C2; k += 4) {
                unsigned long long wp0 = pack2(wa, wb);
                unsigned long long wp1 = pack2(wx, wd);
                int kn = (k + 4 < C2) ? (k + 4) : 0;
                wa = __ldg(wc + kn * CC);
                wb = __ldg(wc + (kn + 1) * CC);
                wx = __ldg(wc + (kn + 2) * CC);
                wd = __ldg(wc + (kn + 3) * CC);
                uint32_t base = hb + k * 4;
                #pragma unroll
                for (int jj = 0; jj < 16; jj++) {
                    unsigned long long s0, s1;
                    lds2(s0, s1, base + jj * (C2 * 4));
                    fma2(acc[jj], s0, wp0);
                    fma2(acc[jj], s1, wp1);
                }
            }
            #pragma unroll
            for (int jj = 0; jj < 16; jj++) {
                float lo, hi; unpack2(acc[jj], lo, hi);
                s.h2[(jh * 16 + jj) * (CC + 1) + oc] = lrelu((lo + hi) * BN_SCALE);
            }
        }
        __syncthreads();

        // --- layer3 + sigmoid ---
        if (tid < 32) {
            float acc = 0.f;
            #pragma unroll 4
            for (int c = 0; c < CC; c++) acc += s.h2[tid * (CC + 1) + c] * s.w3s[c];
            float x = acc + b3v;
            s.erow[j0 + tid] = 1.0f / (1.0f + expf(-x));
        }
        __syncthreads();
    }

    // --- row postprocess ---
    if (tid < NN) s.red[tid] = s.epl[tid];
    __syncthreads();
    for (int st = 64; st > 0; st >>= 1) { if (tid < st) s.red[tid] += s.red[tid + st]; __syncthreads(); }
    const float epsum = s.red[0];
    __syncthreads();

    if (tid < NN) s.erow[tid] *= s.epl[tid];
    __syncthreads();

    if (kval > 0 && kval < NN) {
        int cnt = 0;
        if (tid < NN) {
            float mine = s.erow[tid];
            for (int jj = 0; jj < NN; jj++) {
                float v = s.erow[jj];
                cnt += (v > mine) || (v == mine && jj < tid);
            }
        }
        __syncthreads();
        if (tid < NN && cnt >= kval) s.erow[tid] = 0.f;
        __syncthreads();
    }

    if (tid < NN) s.red[tid] = fabsf(s.erow[tid]);
    __syncthreads();
    for (int st = 64; st > 0; st >>= 1) { if (tid < st) s.red[tid] += s.red[tid + st]; __syncthreads(); }
    const float l1 = s.red[0];
    __syncthreads();

    const float scale = epsum / fmaxf(l1, 1e-12f);
    if (tid < NN)
        s.erow[tid] = s.erow[tid] * scale + ((tid == i) ? 1.0f : 0.0f) + 1e-6f;
    __syncthreads();

    if (tid < NN) s.red[tid] = s.erow[tid];
    __syncthreads();
    for (int st = 64; st > 0; st >>= 1) { if (tid < st) s.red[tid] += s.red[tid + st]; __syncthreads(); }
    const float rsum = s.red[0];
    __syncthreads();

    if (tid < NN) ep_out[row * NN + tid] = s.erow[tid] / rsum;
}

// ---------------------------------------------------------------------------
// Q/K projection
// ---------------------------------------------------------------------------
__global__ void qk_kernel(const float* __restrict__ vp,
                          const float* __restrict__ wq,
                          const float* __restrict__ wk,
                          float* __restrict__ Q,
                          float* __restrict__ K)
{
    __shared__ float vr[CC];
    const int r = blockIdx.x;
    const int tid = threadIdx.x;  // 128
    vr[tid] = vp[r * CC + tid];
    __syncthreads();
    float aq = 0.f, ak = 0.f;
    #pragma unroll 4
    for (int c = 0; c < CC; c++) {
        float v = vr[c];
        aq += v * __ldg(wq + c * CC + tid);
        ak += v * __ldg(wk + c * CC + tid);
    }
    Q[r * CC + tid] = aq;
    K[r * CC + tid] = ak;
}

// ---------------------------------------------------------------------------
// MHA + ep*attn fusion
// ---------------------------------------------------------------------------
struct MhaSmem {
    float q[CC];
    float red[NN];
    float Ks[NN * (CC + 1)];
};

__global__ void mha_kernel(const float* __restrict__ Q,
                           const float* __restrict__ K,
                           const float* __restrict__ ep,
                           float* __restrict__ epattn)
{
    extern __shared__ float smem_raw[];
    MhaSmem& s = *reinterpret_cast<MhaSmem*>(smem_raw);
    const int qi = blockIdx.x;
    const int b = blockIdx.y;
    const int tid = threadIdx.x;  // 128
    const int row = b * NN + qi;

    s.q[tid] = Q[row * CC + tid];
    for (int idx = tid; idx < NN * CC; idx += 128) {
        int j = idx >> 7, c = idx & 127;
        s.Ks[j * (CC + 1) + c] = K[(b * NN + j) * CC + c];
    }
    __syncthreads();

    const float inv = 0.17677669529663687f;
    float acc = 0.f;
    for (int h = 0; h < HH; h++) {
        float sc = 0.f;
        const float* kr = s.Ks + tid * (CC + 1) + h * DKK;
        const float* qr = s.q + h * DKK;
        #pragma unroll
        for (int d = 0; d < DKK; d++) sc += qr[d] * kr[d];
        sc *= inv;

        s.red[tid] = sc;
        __syncthreads();
        for (int st = 64; st > 0; st >>= 1) { if (tid < st) s.red[tid] = fmaxf(s.red[tid], s.red[tid + st]); __syncthreads(); }
        float mx = s.red[0];
        __syncthreads();
        float ex = expf(sc - mx);
        s.red[tid] = ex;
        __syncthreads();
        for (int st = 64; st > 0; st >>= 1) { if (tid < st) s.red[tid] += s.red[tid + st]; __syncthreads(); }
        float sm = s.red[0];
        __syncthreads();
        acc += ex / sm;
    }
    epattn[row * NN + tid] = ep[row * NN + tid] * (acc * 0.25f);
}

// ---------------------------------------------------------------------------
// D2P: one block per (b, 8-row tile). 256 threads.
// ---------------------------------------------------------------------------
struct D2pSmem {
    float vps[NN * CC];       // full vp[b]
    float edge[8 * NN];
    float nf[8 * 2 * CC];
    float hb[8 * 2 * CC];
};

__global__ void d2p_kernel(const float* __restrict__ epattn,
                           const float* __restrict__ vp,
                           const float* __restrict__ w1,
                           const float* __restrict__ w2,
                           float* __restrict__ vp_out)
{
    extern __shared__ float smem_raw[];
    D2pSmem& s = *reinterpret_cast<D2pSmem*>(smem_raw);
    const int it = blockIdx.x;
    const int b = blockIdx.y;
    const int tid = threadIdx.x;  // 256

    for (int idx = tid; idx < NN * CC; idx += 256)
        s.vps[idx] = vp[b * NN * CC + idx];
    __syncthreads();

    // edge rows + nf first half: warp w handles row r=w
    {
        const int w = tid >> 5, lane = tid & 31;
        const int i = it * 8 + w;
        const int row = b * NN + i;
        float e[4];
        float ssum = 0.f;
        #pragma unroll
        for (int q = 0; q < 4; q++) {
            int j = lane + 32 * q;
            float v = epattn[row * NN + j];
            if (j == i) v = 0.f;
            e[q] = v;
            ssum += fabsf(v);
        }
        #pragma unroll
        for (int st = 16; st > 0; st >>= 1) ssum += __shfl_xor_sync(0xffffffffu, ssum, st);
        float inv = 1.0f / fmaxf(ssum, 1e-12f);
        #pragma unroll
        for (int q = 0; q < 4; q++) {
            int j = lane + 32 * q;
            s.edge[w * NN + j] = e[q] * inv;
            s.nf[w * 2 * CC + j] = s.vps[i * CC + j];  // c == j range (CC == NN)
        }
    }
    __syncthreads();

    // aggr: nf[r][CC + c]
    {
        const int c = tid & 127, r0 = tid >> 7;
        float a[4] = {0.f, 0.f, 0.f, 0.f};
        #pragma unroll 2
        for (int j = 0; j < NN; j++) {
            float v = s.vps[j * CC + c];
            #pragma unroll
            for (int q = 0; q < 4; q++) a[q] += s.edge[(r0 + 2 * q) * NN + j] * v;
        }
        #pragma unroll
        for (int q = 0; q < 4; q++) s.nf[(r0 + 2 * q) * 2 * CC + CC + c] = a[q];
    }
    __syncthreads();

    // layer1: o = tid, 8 rows
    {
        float acc[8] = {0.f};
        #pragma unroll 2
        for (int k = 0; k < 2 * CC; k++) {
            float w = __ldg(w1 + k * 2 * CC + tid);
            #pragma unroll
            for (int r = 0; r < 8; r++) acc[r] += s.nf[r * 2 * CC + k] * w;
        }
        #pragma unroll
        for (int r = 0; r < 8; r++) s.hb[r * 2 * CC + tid] = lrelu(acc[r] * BN_SCALE);
    }
    __syncthreads();

    // layer2: oc = tid&127, 4 rows
    {
        const int oc = tid & 127, r0 = tid >> 7;
        float acc[4] = {0.f, 0.f, 0.f, 0.f};
        #pragma unroll 2
        for (int k = 0; k < 2 * CC; k++) {
            float w = __ldg(w2 + k * CC + oc);
            #pragma unroll
            for (int q = 0; q < 4; q++) acc[q] += s.hb[(r0 + 2 * q) * 2 * CC + k] * w;
        }
        #pragma unroll
        for (int q = 0; q < 4; q++)
            vp_out[(b * NN + it * 8 + r0 + 2 * q) * CC + oc] = lrelu(acc[q] * BN_SCALE);
    }
}

// ---------------------------------------------------------------------------

extern "C" void kernel_launch(void* const* d_in, const int* in_sizes, int n_in,
                              void* d_out, int out_size)
{
    const float* vp   = (const float*)d_in[0];
    const float* ep0  = (const float*)d_in[1];
    const float* pw1  = (const float*)d_in[2];
    const float* pw2  = (const float*)d_in[3];
    const float* pw3  = (const float*)d_in[4];
    const float* pb3  = (const float*)d_in[5];
    const float* psw1 = (const float*)d_in[6];
    const float* psw2 = (const float*)d_in[7];
    const float* psw3 = (const float*)d_in[8];
    const float* psb3 = (const float*)d_in[9];
    const float* dw1  = (const float*)d_in[10];
    const float* dw2  = (const float*)d_in[11];
    const float* wq   = (const float*)d_in[12];
    const float* wk   = (const float*)d_in[13];
    float* out = (float*)d_out;

    const int psim_smem = (int)sizeof(PsimSmem);
    const int mha_smem  = (int)sizeof(MhaSmem);
    const int d2p_smem  = (int)sizeof(D2pSmem);
    cudaFuncSetAttribute(psim_kernel, cudaFuncAttributeMaxDynamicSharedMemorySize, psim_smem);
    cudaFuncSetAttribute(mha_kernel,  cudaFuncAttributeMaxDynamicSharedMemorySize, mha_smem);
    cudaFuncSetAttribute(d2p_kernel,  cudaFuncAttributeMaxDynamicSharedMemorySize, d2p_smem);

    float *ep, *epattn, *Q, *K, *vp1, *vp2;
    cudaGetSymbolAddress((void**)&ep, g_ep);
    cudaGetSymbolAddress((void**)&epattn, g_epattn);
    cudaGetSymbolAddress((void**)&Q, g_Q);
    cudaGetSymbolAddress((void**)&K, g_K);
    cudaGetSymbolAddress((void**)&vp1, g_vp1);
    cudaGetSymbolAddress((void**)&vp2, g_vp2);

    dim3 grid(NN, BB);
    dim3 grid_d2p(NN / 8, BB);

    psim_kernel<<<grid, 256, psim_smem>>>(vp, ep0, ep, pw1, pw2, pw3, pb3, 0);

    for (int g = 0; g < 2; g++) {
        const float* vpc = (g == 0) ? vp : vp1;
        float* vpn = (g == 0) ? vp1 : vp2;

        qk_kernel<<<BB * NN, 128>>>(vpc, wq + g * CC * CC, wk + g * CC * CC, Q, K);
        mha_kernel<<<grid, 128, mha_smem>>>(Q, K, ep, epattn);
        d2p_kernel<<<grid_d2p, 256, d2p_smem>>>(epattn, vpc,
                                                dw1 + g * 2 * CC * 2 * CC,
                                                dw2 + g * 2 * CC * CC, vpn);

        const int kv = (g == 0) ? 115 : 102;
        float* epo = (g == 1) ? out : ep;
        psim_kernel<<<grid, 256, psim_smem>>>(vpn, ep, epo,
                                              psw1 + g * CC * C2,
                                              psw2 + g * C2 * CC,
                                              psw3 + g * CC,
                                              psb3 + g, kv);
    }
}

// round 5
// speedup vs baseline: 3.0090x; 2.3359x over previous
#include <cuda_runtime.h>
#include <math.h>
#include <stdint.h>

#define BB 8
#define NN 128
#define CC 128
#define C2 256
#define HH 4
#define DKK 32
#define BN_SCALE 0.9999950000374997f

__device__ float g_ep[BB*NN*NN];
__device__ float g_epattn[BB*NN*NN];
__device__ float g_Q[BB*NN*CC];
__device__ float g_K[BB*NN*CC];
__device__ float g_vp1[BB*NN*CC];
__device__ float g_vp2[BB*NN*CC];
__device__ float g_w1P[3 * 32768];   // fragment-permuted tf32 w1 (per set)
__device__ float g_w2P[3 * 32768];   // fragment-permuted tf32 w2 (per set)

__device__ __forceinline__ float lrelu(float x) { return x > 0.f ? x : 0.01f * x; }
__device__ __forceinline__ uint32_t f2tf(float f) {
    uint32_t u; asm("cvt.rna.tf32.f32 %0, %1;" : "=r"(u) : "f"(f)); return u;
}

// m16n8k8 tf32 mma (A row, B col). Generic PTX, works on sm_103 target.
__device__ __forceinline__ void mma_tf32(float* c, const uint4& a, const uint2& b) {
    asm volatile(
        "mma.sync.aligned.m16n8k8.row.col.f32.tf32.tf32.f32 "
        "{%0,%1,%2,%3}, {%4,%5,%6,%7}, {%8,%9}, {%0,%1,%2,%3};"
        : "+f"(c[0]), "+f"(c[1]), "+f"(c[2]), "+f"(c[3])
        : "r"(a.x), "r"(a.y), "r"(a.z), "r"(a.w), "r"(b.x), "r"(b.y));
}

// ---------------- weight prep: transpose + tf32 + fragment permute ----------
// w1P layout: [ntile=32][kt=16][lane=32][slot=2] floats.
//   element: B[k=c][n=o], o = ntile*8 + (lane>>2), c = kt*8 + (lane&3) + slot*4
// w2P layout: [ntile=16][kt=32][lane=32][slot=2], o2 = ntile*8+(lane>>2), k likewise.
__global__ void prep_weights(const float* __restrict__ w1, const float* __restrict__ w2,
                             float* __restrict__ w1P, float* __restrict__ w2P)
{
    int idx = blockIdx.x * 256 + threadIdx.x;   // 0..32767
    {
        int slot = idx & 1, lane = (idx >> 1) & 31, kt = (idx >> 6) & 15, ntile = idx >> 10;
        int o = ntile * 8 + (lane >> 2);
        int c = kt * 8 + (lane & 3) + slot * 4;
        w1P[idx] = __uint_as_float(f2tf(w1[c * C2 + o]));
    }
    {
        int slot = idx & 1, lane = (idx >> 1) & 31, kt = (idx >> 6) & 31, ntile = idx >> 11;
        int o = ntile * 8 + (lane >> 2);
        int k = kt * 8 + (lane & 3) + slot * 4;
        w2P[idx] = __uint_as_float(f2tf(w2[k * CC + o]));
    }
}

// ---------------- psim via mma.sync ------------------------------------------
// smem layout (bytes):
#define MS_SIMP 0          // 65536: sim A-perm [kt=16][wm=8][lane]float4
#define MS_H1P  65536      // 131072: h1 A-perm [kt=32][wm=8][lane]float4
#define MS_WBUF 196608     // 16384: weight chunk
#define MS_VPI  212992
#define MS_W3S  213504
#define MS_EPL  214016
#define MS_EROW 214528
#define MS_RED  215040
#define SMEM_PS 215552

__device__ __forceinline__ void h1_store(char* smem, int j, int o, float v) {
    uint32_t off = (uint32_t)((((o >> 3) * 8 + (j >> 4)) * 32 + ((j & 7) << 2) + (o & 3)) * 16
                   + (((j >> 3) & 1) + (((o >> 2) & 1) << 1)) * 4);
    *(uint32_t*)(smem + MS_H1P + off) = f2tf(lrelu(v * BN_SCALE));
}

__global__ void __launch_bounds__(256, 1)
psim_mma(const float* __restrict__ vp,
         const float* __restrict__ ep_in,
         float* __restrict__ ep_out,
         const float* __restrict__ w1P,
         const float* __restrict__ w2P,
         const float* __restrict__ w3,
         const float* __restrict__ b3,
         int kval)
{
    extern __shared__ char smem[];
    float* s_vpi  = (float*)(smem + MS_VPI);
    float* s_w3   = (float*)(smem + MS_W3S);
    float* s_epl  = (float*)(smem + MS_EPL);
    float* s_erow = (float*)(smem + MS_EROW);
    float* s_red  = (float*)(smem + MS_RED);
    const int i = blockIdx.x, b = blockIdx.y;
    const int tid = threadIdx.x, w = tid >> 5, lane = tid & 31;
    const int row = b * NN + i;

    if (tid < 128) {
        s_vpi[tid] = vp[row * CC + tid];
        s_w3[tid]  = w3[tid];
        float v = ep_in[row * NN + tid];
        s_epl[tid] = (tid == i) ? 0.f : v;
    }
    __syncthreads();
    const float b3v = b3[0];

    // build sim A-perm: element (j,c) -> tf32((vpi[c]-vp[j,c])^2)
    for (int q = tid; q < 4096; q += 256) {
        int j = q >> 5, c0 = (q & 31) << 2;
        const float4 vj = *(const float4*)(vp + (b * NN + j) * CC + c0);
        const float4 vi = *(const float4*)(s_vpi + c0);
        float d0 = vi.x - vj.x, d1 = vi.y - vj.y, d2 = vi.z - vj.z, d3 = vi.w - vj.w;
        int slot = ((j >> 3) & 1) + (((c0 >> 2) & 1) << 1);
        uint32_t base = (uint32_t)((((c0 >> 3) * 8 + (j >> 4)) * 32 + ((j & 7) << 2)) * 16 + slot * 4);
        *(uint32_t*)(smem + MS_SIMP + base)      = f2tf(d0 * d0);
        *(uint32_t*)(smem + MS_SIMP + base + 16) = f2tf(d1 * d1);
        *(uint32_t*)(smem + MS_SIMP + base + 32) = f2tf(d2 * d2);
        *(uint32_t*)(smem + MS_SIMP + base + 48) = f2tf(d3 * d3);
    }
    __syncthreads();

    const int r0 = (w << 4) + (lane >> 2);  // this thread's D rows: r0, r0+8

    // ---- GEMM1: D1[128j,256o] = sim @ w1^T, 8 chunks of 32 o ----
    for (int ch = 0; ch < 8; ch++) {
        {
            const float4* src = (const float4*)(w1P + ch * 4096);
            float4* dst = (float4*)(smem + MS_WBUF);
            #pragma unroll
            for (int t = 0; t < 4; t++) dst[tid + t * 256] = src[tid + t * 256];
        }
        __syncthreads();
        float acc[4][4];
        #pragma unroll
        for (int nt = 0; nt < 4; nt++)
            #pragma unroll
            for (int t = 0; t < 4; t++) acc[nt][t] = 0.f;
        #pragma unroll 4
        for (int kt = 0; kt < 16; kt++) {
            uint4 a = *(const uint4*)(smem + MS_SIMP + ((kt * 8 + w) * 32 + lane) * 16);
            #pragma unroll
            for (int nt = 0; nt < 4; nt++) {
                uint2 bf = *(const uint2*)(smem + MS_WBUF + ((nt * 16 + kt) * 32 + lane) * 8);
                mma_tf32(acc[nt], a, bf);
            }
        }
        #pragma unroll
        for (int nt = 0; nt < 4; nt++) {
            int ob = (ch << 5) + (nt << 3) + ((lane & 3) << 1);
            h1_store(smem, r0,     ob,     acc[nt][0]);
            h1_store(smem, r0,     ob + 1, acc[nt][1]);
            h1_store(smem, r0 + 8, ob,     acc[nt][2]);
            h1_store(smem, r0 + 8, ob + 1, acc[nt][3]);
        }
        __syncthreads();
    }

    // ---- GEMM2 + layer3 partials: D2[128j,128o2] = h1 @ w2^T, 8 chunks of 16 o ----
    float pr0 = 0.f, pr1 = 0.f;
    for (int ch = 0; ch < 8; ch++) {
        {
            const float4* src = (const float4*)(w2P + ch * 4096);
            float4* dst = (float4*)(smem + MS_WBUF);
            #pragma unroll
            for (int t = 0; t < 4; t++) dst[tid + t * 256] = src[tid + t * 256];
        }
        __syncthreads();
        float acc[2][4];
        #pragma unroll
        for (int nt = 0; nt < 2; nt++)
            #pragma unroll
            for (int t = 0; t < 4; t++) acc[nt][t] = 0.f;
        #pragma unroll 4
        for (int kt = 0; kt < 32; kt++) {
            uint4 a = *(const uint4*)(smem + MS_H1P + ((kt * 8 + w) * 32 + lane) * 16);
            #pragma unroll
            for (int nt = 0; nt < 2; nt++) {
                uint2 bf = *(const uint2*)(smem + MS_WBUF + ((nt * 32 + kt) * 32 + lane) * 8);
                mma_tf32(acc[nt], a, bf);
            }
        }
        #pragma unroll
        for (int nt = 0; nt < 2; nt++) {
            int ob = (ch << 4) + (nt << 3) + ((lane & 3) << 1);
            float wa = s_w3[ob], wb = s_w3[ob + 1];
            pr0 += lrelu(acc[nt][0] * BN_SCALE) * wa + lrelu(acc[nt][1] * BN_SCALE) * wb;
            pr1 += lrelu(acc[nt][2] * BN_SCALE) * wa + lrelu(acc[nt][3] * BN_SCALE) * wb;
        }
        __syncthreads();
    }
    pr0 += __shfl_xor_sync(0xffffffffu, pr0, 1);
    pr0 += __shfl_xor_sync(0xffffffffu, pr0, 2);
    pr1 += __shfl_xor_sync(0xffffffffu, pr1, 1);
    pr1 += __shfl_xor_sync(0xffffffffu, pr1, 2);
    if ((lane & 3) == 0) {
        s_erow[r0]     = 1.0f / (1.0f + expf(-(pr0 + b3v)));
        s_erow[r0 + 8] = 1.0f / (1.0f + expf(-(pr1 + b3v)));
    }
    __syncthreads();

    // ---- row postprocess ----
    if (tid < 128) s_red[tid] = s_epl[tid];
    __syncthreads();
    for (int st = 64; st > 0; st >>= 1) { if (tid < st) s_red[tid] += s_red[tid + st]; __syncthreads(); }
    const float epsum = s_red[0];
    __syncthreads();

    if (tid < 128) s_erow[tid] *= s_epl[tid];
    __syncthreads();

    if (kval > 0 && kval < NN) {
        int cnt = 0;
        if (tid < 128) {
            float mine = s_erow[tid];
            for (int jj = 0; jj < NN; jj++) {
                float v = s_erow[jj];
                cnt += (v > mine) || (v == mine && jj < tid);
            }
        }
        __syncthreads();
        if (tid < 128 && cnt >= kval) s_erow[tid] = 0.f;
        __syncthreads();
    }

    if (tid < 128) s_red[tid] = fabsf(s_erow[tid]);
    __syncthreads();
    for (int st = 64; st > 0; st >>= 1) { if (tid < st) s_red[tid] += s_red[tid + st]; __syncthreads(); }
    const float l1 = s_red[0];
    __syncthreads();

    const float scale = epsum / fmaxf(l1, 1e-12f);
    if (tid < 128)
        s_erow[tid] = s_erow[tid] * scale + ((tid == i) ? 1.0f : 0.0f) + 1e-6f;
    __syncthreads();

    if (tid < 128) s_red[tid] = s_erow[tid];
    __syncthreads();
    for (int st = 64; st > 0; st >>= 1) { if (tid < st) s_red[tid] += s_red[tid + st]; __syncthreads(); }
    const float rsum = s_red[0];
    __syncthreads();

    if (tid < 128) ep_out[row * NN + tid] = s_erow[tid] / rsum;
}

// ---------------- Q/K projection -------------------------------------------
__global__ void qk_kernel(const float* __restrict__ vp,
                          const float* __restrict__ wq,
                          const float* __restrict__ wk,
                          float* __restrict__ Q,
                          float* __restrict__ K)
{
    __shared__ float vr[CC];
    const int r = blockIdx.x;
    const int tid = threadIdx.x;  // 128
    vr[tid] = vp[r * CC + tid];
    __syncthreads();
    float aq = 0.f, ak = 0.f;
    #pragma unroll 4
    for (int c = 0; c < CC; c++) {
        float v = vr[c];
        aq += v * __ldg(wq + c * CC + tid);
        ak += v * __ldg(wk + c * CC + tid);
    }
    Q[r * CC + tid] = aq;
    K[r * CC + tid] = ak;
}

// ---------------- MHA + ep*attn --------------------------------------------
struct MhaSmem {
    float q[CC];
    float red[NN];
    float Ks[NN * (CC + 1)];
};

__global__ void mha_kernel(const float* __restrict__ Q,
                           const float* __restrict__ K,
                           const float* __restrict__ ep,
                           float* __restrict__ epattn)
{
    extern __shared__ float smem_raw[];
    MhaSmem& s = *reinterpret_cast<MhaSmem*>(smem_raw);
    const int qi = blockIdx.x;
    const int b = blockIdx.y;
    const int tid = threadIdx.x;  // 128
    const int row = b * NN + qi;

    s.q[tid] = Q[row * CC + tid];
    for (int idx = tid; idx < NN * CC; idx += 128) {
        int j = idx >> 7, c = idx & 127;
        s.Ks[j * (CC + 1) + c] = K[(b * NN + j) * CC + c];
    }
    __syncthreads();

    const float inv = 0.17677669529663687f;
    float acc = 0.f;
    for (int h = 0; h < HH; h++) {
        float sc = 0.f;
        const float* kr = s.Ks + tid * (CC + 1) + h * DKK;
        const float* qr = s.q + h * DKK;
        #pragma unroll
        for (int d = 0; d < DKK; d++) sc += qr[d] * kr[d];
        sc *= inv;

        s.red[tid] = sc;
        __syncthreads();
        for (int st = 64; st > 0; st >>= 1) { if (tid < st) s.red[tid] = fmaxf(s.red[tid], s.red[tid + st]); __syncthreads(); }
        float mx = s.red[0];
        __syncthreads();
        float ex = expf(sc - mx);
        s.red[tid] = ex;
        __syncthreads();
        for (int st = 64; st > 0; st >>= 1) { if (tid < st) s.red[tid] += s.red[tid + st]; __syncthreads(); }
        float sm = s.red[0];
        __syncthreads();
        acc += ex / sm;
    }
    epattn[row * NN + tid] = ep[row * NN + tid] * (acc * 0.25f);
}

// ---------------- D2P: 4 rows/block, 256 threads ----------------------------
__global__ void __launch_bounds__(256)
d2p_kernel(const float* __restrict__ epattn,
           const float* __restrict__ vp,
           const float* __restrict__ w1,
           const float* __restrict__ w2,
           float* __restrict__ vp_out)
{
    __shared__ float edge[4][NN];
    __shared__ float nf[4][2 * CC];
    __shared__ float hb[4][2 * CC];
    const int it = blockIdx.x;   // 0..31
    const int b = blockIdx.y;
    const int tid = threadIdx.x; // 256
    const int wid = tid >> 5, lane = tid & 31;

    if (wid < 4) {
        const int i = it * 4 + wid;
        const int row = b * NN + i;
        float e[4];
        float ssum = 0.f;
        #pragma unroll
        for (int q = 0; q < 4; q++) {
            int j = lane + 32 * q;
            float v = epattn[row * NN + j];
            if (j == i) v = 0.f;
            e[q] = v;
            ssum += fabsf(v);
        }
        #pragma unroll
        for (int st = 16; st > 0; st >>= 1) ssum += __shfl_xor_sync(0xffffffffu, ssum, st);
        float inv = 1.0f / fmaxf(ssum, 1e-12f);
        #pragma unroll
        for (int q = 0; q < 4; q++) {
            int j = lane + 32 * q;
            edge[wid][j] = e[q] * inv;
            nf[wid][j] = vp[row * CC + j];
        }
    }
    __syncthreads();

    {
        const int c = tid & 127, rr = tid >> 7;  // rr in {0,1} -> rows rr, rr+2
        float a0 = 0.f, a1 = 0.f;
        #pragma unroll 4
        for (int j = 0; j < NN; j++) {
            float v = __ldg(vp + (b * NN + j) * CC + c);
            a0 += edge[rr][j] * v;
            a1 += edge[rr + 2][j] * v;
        }
        nf[rr][CC + c] = a0;
        nf[rr + 2][CC + c] = a1;
    }
    __syncthreads();

    {
        float acc[4] = {0.f, 0.f, 0.f, 0.f};
        #pragma unroll 4
        for (int k = 0; k < 2 * CC; k++) {
            float w = __ldg(w1 + k * 2 * CC + tid);
            #pragma unroll
            for (int r = 0; r < 4; r++) acc[r] += nf[r][k] * w;
        }
        #pragma unroll
        for (int r = 0; r < 4; r++) hb[r][tid] = lrelu(acc[r] * BN_SCALE);
    }
    __syncthreads();

    {
        const int oc = tid & 127, rr = tid >> 7;
        float a0 = 0.f, a1 = 0.f;
        #pragma unroll 4
        for (int k = 0; k < 2 * CC; k++) {
            float w = __ldg(w2 + k * CC + oc);
            a0 += hb[rr][k] * w;
            a1 += hb[rr + 2][k] * w;
        }
        vp_out[(b * NN + it * 4 + rr) * CC + oc] = lrelu(a0 * BN_SCALE);
        vp_out[(b * NN + it * 4 + rr + 2) * CC + oc] = lrelu(a1 * BN_SCALE);
    }
}

// ---------------------------------------------------------------------------

extern "C" void kernel_launch(void* const* d_in, const int* in_sizes, int n_in,
                              void* d_out, int out_size)
{
    const float* vp   = (const float*)d_in[0];
    const float* ep0  = (const float*)d_in[1];
    const float* pw1  = (const float*)d_in[2];
    const float* pw2  = (const float*)d_in[3];
    const float* pw3  = (const float*)d_in[4];
    const float* pb3  = (const float*)d_in[5];
    const float* psw1 = (const float*)d_in[6];
    const float* psw2 = (const float*)d_in[7];
    const float* psw3 = (const float*)d_in[8];
    const float* psb3 = (const float*)d_in[9];
    const float* dw1  = (const float*)d_in[10];
    const float* dw2  = (const float*)d_in[11];
    const float* wq   = (const float*)d_in[12];
    const float* wk   = (const float*)d_in[13];
    float* out = (float*)d_out;

    const int mha_smem = (int)sizeof(MhaSmem);
    cudaFuncSetAttribute(psim_mma, cudaFuncAttributeMaxDynamicSharedMemorySize, SMEM_PS);
    cudaFuncSetAttribute(mha_kernel, cudaFuncAttributeMaxDynamicSharedMemorySize, mha_smem);

    float *ep, *epattn, *Q, *K, *vp1, *vp2, *w1P, *w2P;
    cudaGetSymbolAddress((void**)&ep, g_ep);
    cudaGetSymbolAddress((void**)&epattn, g_epattn);
    cudaGetSymbolAddress((void**)&Q, g_Q);
    cudaGetSymbolAddress((void**)&K, g_K);
    cudaGetSymbolAddress((void**)&vp1, g_vp1);
    cudaGetSymbolAddress((void**)&vp2, g_vp2);
    cudaGetSymbolAddress((void**)&w1P, g_w1P);
    cudaGetSymbolAddress((void**)&w2P, g_w2P);

    // precompute permuted tf32 weights: set0=pre, set1=g0, set2=g1
    prep_weights<<<128, 256>>>(pw1, pw2, w1P, w2P);
    prep_weights<<<128, 256>>>(psw1, psw2, w1P + 32768, w2P + 32768);
    prep_weights<<<128, 256>>>(psw1 + CC * C2, psw2 + C2 * CC, w1P + 2 * 32768, w2P + 2 * 32768);

    dim3 grid(NN, BB);
    dim3 grid_d2p(NN / 4, BB);

    psim_mma<<<grid, 256, SMEM_PS>>>(vp, ep0, ep, w1P, w2P, pw3, pb3, 0);

    for (int g = 0; g < 2; g++) {
        const float* vpc = (g == 0) ? vp : vp1;
        float* vpn = (g == 0) ? vp1 : vp2;

        qk_kernel<<<BB * NN, 128>>>(vpc, wq + g * CC * CC, wk + g * CC * CC, Q, K);
        mha_kernel<<<grid, 128, mha_smem>>>(Q, K, ep, epattn);
        d2p_kernel<<<grid_d2p, 256>>>(epattn, vpc,
                                      dw1 + g * 2 * CC * 2 * CC,
                                      dw2 + g * 2 * CC * CC, vpn);

        const int kv = (g == 0) ? 115 : 102;
        float* epo = (g == 1) ? out : ep;
        psim_mma<<<grid, 256, SMEM_PS>>>(vpn, ep, epo,
                                         w1P + (g + 1) * 32768,
                                         w2P + (g + 1) * 32768,
                                         psw3 + g * CC,
                                         psb3 + g, kv);
    }
}

// round 6
// speedup vs baseline: 3.7915x; 1.2600x over previous
#include <cuda_runtime.h>
#include <math.h>
#include <stdint.h>

#define BB 8
#define NN 128
#define CC 128
#define C2 256
#define HH 4
#define DKK 32
#define BN_SCALE 0.9999950000374997f

__device__ float g_ep[BB*NN*NN];
__device__ float g_epattn[BB*NN*NN];
__device__ float g_Q[BB*NN*CC];
__device__ float g_K[BB*NN*CC];
__device__ float g_vp1[BB*NN*CC];
__device__ float g_vp2[BB*NN*CC];
__device__ float g_w1P[3 * 32768];   // [npair16][kt16][lane32][slot4] per set
__device__ float g_w2P[3 * 32768];   // [khalf2][npair8][ktl16][lane32][slot4] per set

__device__ __forceinline__ float lrelu(float x) { return x > 0.f ? x : 0.01f * x; }
__device__ __forceinline__ uint32_t f2tf(float f) {
    uint32_t u; asm("cvt.rna.tf32.f32 %0, %1;" : "=r"(u) : "f"(f)); return u;
}

__device__ __forceinline__ void mma_tf32(float* c, const uint4& a, uint32_t b0, uint32_t b1) {
    asm volatile(
        "mma.sync.aligned.m16n8k8.row.col.f32.tf32.tf32.f32 "
        "{%0,%1,%2,%3}, {%4,%5,%6,%7}, {%8,%9}, {%0,%1,%2,%3};"
        : "+f"(c[0]), "+f"(c[1]), "+f"(c[2]), "+f"(c[3])
        : "r"(a.x), "r"(a.y), "r"(a.z), "r"(a.w), "r"(b0), "r"(b1));
}

// ---------------- weight prep -----------------------------------------------
// w1P: [npair][kt][lane][slot]: nt = npair*2+(slot>>1), k = kt*8+(lane&3)+(slot&1)*4,
//      o = nt*8+(lane>>2), val = tf32(w1[k*256+o])
// w2P: [khalf][npair][ktl][lane][slot]: kt2 = khalf*16+ktl, k = kt2*8+(lane&3)+(slot&1)*4,
//      o = (npair*2+(slot>>1))*8+(lane>>2), val = tf32(w2[k*128+o])
__global__ void prep_weights(const float* __restrict__ w1, const float* __restrict__ w2,
                             float* __restrict__ w1P, float* __restrict__ w2P)
{
    int idx = blockIdx.x * 256 + threadIdx.x;   // 0..32767
    {
        int slot = idx & 3, lane = (idx >> 2) & 31, kt = (idx >> 7) & 15, npair = idx >> 11;
        int nt = npair * 2 + (slot >> 1);
        int k = kt * 8 + (lane & 3) + (slot & 1) * 4;
        int o = nt * 8 + (lane >> 2);
        w1P[idx] = __uint_as_float(f2tf(w1[k * C2 + o]));
    }
    {
        int slot = idx & 3, lane = (idx >> 2) & 31, ktl = (idx >> 7) & 15, npair = (idx >> 11) & 7, kh = idx >> 14;
        int kt2 = kh * 16 + ktl;
        int nt = npair * 2 + (slot >> 1);
        int k = kt2 * 8 + (lane & 3) + (slot & 1) * 4;
        int o = nt * 8 + (lane >> 2);
        w2P[idx] = __uint_as_float(f2tf(w2[k * CC + o]));
    }
}

// ---------------- psim via mma.sync ------------------------------------------
#define MS_SIMP 0          // 64KB: sim A-frags [kt16][mt8][lane][4]; later w2 stage
#define MS_H1P  65536      // 128KB: h1 A-frags [kt2 32][mt8][lane][4]
#define MS_WBUF 196608     // 16KB: w1 chunk
#define MS_VPI  212992
#define MS_W3S  213504
#define MS_EPL  214016
#define MS_EROW 214528
#define MS_RED  215040
#define MS_L3   215552     // 2*128 floats
#define SMEM_PS 216576

__device__ __forceinline__ void h1_store(char* smem, int j, int o, float v) {
    uint32_t off = (uint32_t)((((o >> 3) * 8 + (j >> 4)) * 32 + ((j & 7) << 2) + (o & 3)) * 16
                   + (((j >> 3) & 1) + (((o >> 2) & 1) << 1)) * 4);
    *(uint32_t*)(smem + MS_H1P + off) = f2tf(lrelu(v * BN_SCALE));
}

__global__ void __launch_bounds__(256, 1)
psim_mma(const float* __restrict__ vp,
         const float* __restrict__ ep_in,
         float* __restrict__ ep_out,
         const float* __restrict__ w1P,
         const float* __restrict__ w2P,
         const float* __restrict__ w3,
         const float* __restrict__ b3,
         int kval)
{
    extern __shared__ char smem[];
    float* s_vpi  = (float*)(smem + MS_VPI);
    float* s_w3   = (float*)(smem + MS_W3S);
    float* s_epl  = (float*)(smem + MS_EPL);
    float* s_erow = (float*)(smem + MS_EROW);
    float* s_red  = (float*)(smem + MS_RED);
    float* s_l3   = (float*)(smem + MS_L3);
    const int i = blockIdx.x, b = blockIdx.y;
    const int tid = threadIdx.x, w = tid >> 5, lane = tid & 31;
    const int wm = w & 3, wn = w >> 2;
    const int row = b * NN + i;

    if (tid < 128) {
        s_vpi[tid] = vp[row * CC + tid];
        s_w3[tid]  = w3[tid];
        float v = ep_in[row * NN + tid];
        s_epl[tid] = (tid == i) ? 0.f : v;
    }
    __syncthreads();

    // build sim A-frag layout
    for (int q = tid; q < 4096; q += 256) {
        int j = q >> 5, c0 = (q & 31) << 2;
        const float4 vj = *(const float4*)(vp + (b * NN + j) * CC + c0);
        const float4 vi = *(const float4*)(s_vpi + c0);
        float d0 = vi.x - vj.x, d1 = vi.y - vj.y, d2 = vi.z - vj.z, d3 = vi.w - vj.w;
        int slot = ((j >> 3) & 1) + (((c0 >> 2) & 1) << 1);
        uint32_t base = (uint32_t)((((c0 >> 3) * 8 + (j >> 4)) * 32 + ((j & 7) << 2)) * 16 + slot * 4);
        *(uint32_t*)(smem + MS_SIMP + base)      = f2tf(d0 * d0);
        *(uint32_t*)(smem + MS_SIMP + base + 16) = f2tf(d1 * d1);
        *(uint32_t*)(smem + MS_SIMP + base + 32) = f2tf(d2 * d2);
        *(uint32_t*)(smem + MS_SIMP + base + 48) = f2tf(d3 * d3);
    }
    __syncthreads();

    // A fragments resident in registers (rows wm*32 .. wm*32+32)
    uint4 Areg[16][2];
    #pragma unroll
    for (int kt = 0; kt < 16; kt++)
        #pragma unroll
        for (int m = 0; m < 2; m++)
            Areg[kt][m] = *(const uint4*)(smem + MS_SIMP + ((kt * 8 + wm * 2 + m) * 32 + lane) * 16);

    // ---- GEMM1: 8 chunks of 32 o; warp handles npair = ch*2 + wn (16 o) ----
    const uint4* w1Pv = (const uint4*)w1P;
    uint4 pf[4];
    #pragma unroll
    for (int t = 0; t < 4; t++) pf[t] = __ldg(w1Pv + tid + t * 256);

    for (int ch = 0; ch < 8; ch++) {
        #pragma unroll
        for (int t = 0; t < 4; t++)
            *(uint4*)(smem + MS_WBUF + (tid + t * 256) * 16) = pf[t];
        __syncthreads();
        if (ch < 7) {
            #pragma unroll
            for (int t = 0; t < 4; t++) pf[t] = __ldg(w1Pv + (ch + 1) * 1024 + tid + t * 256);
        }
        float acc[2][2][4];
        #pragma unroll
        for (int m = 0; m < 2; m++)
            #pragma unroll
            for (int n = 0; n < 2; n++)
                #pragma unroll
                for (int t = 0; t < 4; t++) acc[m][n][t] = 0.f;
        #pragma unroll
        for (int kt = 0; kt < 16; kt++) {
            uint4 W = *(const uint4*)(smem + MS_WBUF + ((wn * 16 + kt) * 32 + lane) * 16);
            mma_tf32(acc[0][0], Areg[kt][0], W.x, W.y);
            mma_tf32(acc[0][1], Areg[kt][0], W.z, W.w);
            mma_tf32(acc[1][0], Areg[kt][1], W.x, W.y);
            mma_tf32(acc[1][1], Areg[kt][1], W.z, W.w);
        }
        #pragma unroll
        for (int m = 0; m < 2; m++)
            #pragma unroll
            for (int ntl = 0; ntl < 2; ntl++) {
                int o = ((ch * 2 + wn) * 2 + ntl) * 8 + (lane & 3) * 2;
                int j = wm * 32 + m * 16 + (lane >> 2);
                h1_store(smem, j,     o,     acc[m][ntl][0]);
                h1_store(smem, j,     o + 1, acc[m][ntl][1]);
                h1_store(smem, j + 8, o,     acc[m][ntl][2]);
                h1_store(smem, j + 8, o + 1, acc[m][ntl][3]);
            }
        __syncthreads();
    }

    // ---- GEMM2: warp covers o-half wn (64 o, 8 nt); B staged in 2 k-halves ----
    float acc2[2][8][4];
    #pragma unroll
    for (int m = 0; m < 2; m++)
        #pragma unroll
        for (int n = 0; n < 8; n++)
            #pragma unroll
            for (int t = 0; t < 4; t++) acc2[m][n][t] = 0.f;

    const uint4* w2Pv = (const uint4*)w2P;
    for (int kh = 0; kh < 2; kh++) {
        uint4 pf2[16];
        #pragma unroll
        for (int t = 0; t < 16; t++) pf2[t] = __ldg(w2Pv + kh * 4096 + tid + t * 256);
        __syncthreads();   // prior readers of sim region done
        #pragma unroll
        for (int t = 0; t < 16; t++)
            *(uint4*)(smem + MS_SIMP + (tid + t * 256) * 16) = pf2[t];
        __syncthreads();
        #pragma unroll 4
        for (int ktl = 0; ktl < 16; ktl++) {
            int kt2 = kh * 16 + ktl;
            uint4 A0 = *(const uint4*)(smem + MS_H1P + ((kt2 * 8 + wm * 2) * 32 + lane) * 16);
            uint4 A1 = *(const uint4*)(smem + MS_H1P + ((kt2 * 8 + wm * 2 + 1) * 32 + lane) * 16);
            #pragma unroll
            for (int p = 0; p < 4; p++) {
                uint4 W = *(const uint4*)(smem + MS_SIMP + (((wn * 4 + p) * 16 + ktl) * 32 + lane) * 16);
                mma_tf32(acc2[0][p * 2],     A0, W.x, W.y);
                mma_tf32(acc2[0][p * 2 + 1], A0, W.z, W.w);
                mma_tf32(acc2[1][p * 2],     A1, W.x, W.y);
                mma_tf32(acc2[1][p * 2 + 1], A1, W.z, W.w);
            }
        }
    }

    // ---- layer3 partials + reduce ----
    const float b3v = b3[0];
    float pr[4] = {0.f, 0.f, 0.f, 0.f};
    #pragma unroll
    for (int m = 0; m < 2; m++)
        #pragma unroll
        for (int p = 0; p < 4; p++)
            #pragma unroll
            for (int ntl = 0; ntl < 2; ntl++) {
                int o = ((wn * 4 + p) * 2 + ntl) * 8 + (lane & 3) * 2;
                float wa = s_w3[o], wb = s_w3[o + 1];
                int q = p * 2 + ntl;
                pr[m * 2]     += lrelu(acc2[m][q][0] * BN_SCALE) * wa + lrelu(acc2[m][q][1] * BN_SCALE) * wb;
                pr[m * 2 + 1] += lrelu(acc2[m][q][2] * BN_SCALE) * wa + lrelu(acc2[m][q][3] * BN_SCALE) * wb;
            }
    #pragma unroll
    for (int t = 0; t < 4; t++) {
        pr[t] += __shfl_xor_sync(0xffffffffu, pr[t], 1);
        pr[t] += __shfl_xor_sync(0xffffffffu, pr[t], 2);
    }
    if ((lane & 3) == 0) {
        int g = lane >> 2;
        s_l3[wn * 128 + wm * 32 + g]      = pr[0];
        s_l3[wn * 128 + wm * 32 + g + 8]  = pr[1];
        s_l3[wn * 128 + wm * 32 + g + 16] = pr[2];
        s_l3[wn * 128 + wm * 32 + g + 24] = pr[3];
    }
    __syncthreads();
    if (tid < 128) {
        float e = s_l3[tid] + s_l3[128 + tid];
        s_erow[tid] = 1.0f / (1.0f + expf(-(e + b3v)));
    }
    __syncthreads();

    // ---- row postprocess ----
    if (tid < 128) s_red[tid] = s_epl[tid];
    __syncthreads();
    for (int st = 64; st > 0; st >>= 1) { if (tid < st) s_red[tid] += s_red[tid + st]; __syncthreads(); }
    const float epsum = s_red[0];
    __syncthreads();

    if (tid < 128) s_erow[tid] *= s_epl[tid];
    __syncthreads();

    if (kval > 0 && kval < NN) {
        int cnt = 0;
        if (tid < 128) {
            float mine = s_erow[tid];
            for (int jj = 0; jj < NN; jj++) {
                float v = s_erow[jj];
                cnt += (v > mine) || (v == mine && jj < tid);
            }
        }
        __syncthreads();
        if (tid < 128 && cnt >= kval) s_erow[tid] = 0.f;
        __syncthreads();
    }

    if (tid < 128) s_red[tid] = fabsf(s_erow[tid]);
    __syncthreads();
    for (int st = 64; st > 0; st >>= 1) { if (tid < st) s_red[tid] += s_red[tid + st]; __syncthreads(); }
    const float l1 = s_red[0];
    __syncthreads();

    const float scale = epsum / fmaxf(l1, 1e-12f);
    if (tid < 128)
        s_erow[tid] = s_erow[tid] * scale + ((tid == i) ? 1.0f : 0.0f) + 1e-6f;
    __syncthreads();

    if (tid < 128) s_red[tid] = s_erow[tid];
    __syncthreads();
    for (int st = 64; st > 0; st >>= 1) { if (tid < st) s_red[tid] += s_red[tid + st]; __syncthreads(); }
    const float rsum = s_red[0];
    __syncthreads();

    if (tid < 128) ep_out[row * NN + tid] = s_erow[tid] / rsum;
}

// ---------------- Q/K projection -------------------------------------------
__global__ void qk_kernel(const float* __restrict__ vp,
                          const float* __restrict__ wq,
                          const float* __restrict__ wk,
                          float* __restrict__ Q,
                          float* __restrict__ K)
{
    __shared__ float vr[CC];
    const int r = blockIdx.x;
    const int tid = threadIdx.x;  // 128
    vr[tid] = vp[r * CC + tid];
    __syncthreads();
    float aq = 0.f, ak = 0.f;
    #pragma unroll 4
    for (int c = 0; c < CC; c++) {
        float v = vr[c];
        aq += v * __ldg(wq + c * CC + tid);
        ak += v * __ldg(wk + c * CC + tid);
    }
    Q[r * CC + tid] = aq;
    K[r * CC + tid] = ak;
}

// ---------------- MHA + ep*attn --------------------------------------------
struct MhaSmem {
    float q[CC];
    float red[NN];
    float Ks[NN * (CC + 1)];
};

__global__ void mha_kernel(const float* __restrict__ Q,
                           const float* __restrict__ K,
                           const float* __restrict__ ep,
                           float* __restrict__ epattn)
{
    extern __shared__ float smem_raw[];
    MhaSmem& s = *reinterpret_cast<MhaSmem*>(smem_raw);
    const int qi = blockIdx.x;
    const int b = blockIdx.y;
    const int tid = threadIdx.x;  // 128
    const int row = b * NN + qi;

    s.q[tid] = Q[row * CC + tid];
    for (int idx = tid; idx < NN * CC; idx += 128) {
        int j = idx >> 7, c = idx & 127;
        s.Ks[j * (CC + 1) + c] = K[(b * NN + j) * CC + c];
    }
    __syncthreads();

    const float inv = 0.17677669529663687f;
    float acc = 0.f;
    for (int h = 0; h < HH; h++) {
        float sc = 0.f;
        const float* kr = s.Ks + tid * (CC + 1) + h * DKK;
        const float* qr = s.q + h * DKK;
        #pragma unroll
        for (int d = 0; d < DKK; d++) sc += qr[d] * kr[d];
        sc *= inv;

        s.red[tid] = sc;
        __syncthreads();
        for (int st = 64; st > 0; st >>= 1) { if (tid < st) s.red[tid] = fmaxf(s.red[tid], s.red[tid + st]); __syncthreads(); }
        float mx = s.red[0];
        __syncthreads();
        float ex = expf(sc - mx);
        s.red[tid] = ex;
        __syncthreads();
        for (int st = 64; st > 0; st >>= 1) { if (tid < st) s.red[tid] += s.red[tid + st]; __syncthreads(); }
        float sm = s.red[0];
        __syncthreads();
        acc += ex / sm;
    }
    epattn[row * NN + tid] = ep[row * NN + tid] * (acc * 0.25f);
}

// ---------------- D2P: 4 rows/block, 256 threads ----------------------------
__global__ void __launch_bounds__(256)
d2p_kernel(const float* __restrict__ epattn,
           const float* __restrict__ vp,
           const float* __restrict__ w1,
           const float* __restrict__ w2,
           float* __restrict__ vp_out)
{
    __shared__ float edge[4][NN];
    __shared__ float nf[4][2 * CC];
    __shared__ float hb[4][2 * CC];
    const int it = blockIdx.x;
    const int b = blockIdx.y;
    const int tid = threadIdx.x;
    const int wid = tid >> 5, lane = tid & 31;

    if (wid < 4) {
        const int i = it * 4 + wid;
        const int row = b * NN + i;
        float e[4];
        float ssum = 0.f;
        #pragma unroll
        for (int q = 0; q < 4; q++) {
            int j = lane + 32 * q;
            float v = epattn[row * NN + j];
            if (j == i) v = 0.f;
            e[q] = v;
            ssum += fabsf(v);
        }
        #pragma unroll
        for (int st = 16; st > 0; st >>= 1) ssum += __shfl_xor_sync(0xffffffffu, ssum, st);
        float inv = 1.0f / fmaxf(ssum, 1e-12f);
        #pragma unroll
        for (int q = 0; q < 4; q++) {
            int j = lane + 32 * q;
            edge[wid][j] = e[q] * inv;
            nf[wid][j] = vp[row * CC + j];
        }
    }
    __syncthreads();

    {
        const int c = tid & 127, rr = tid >> 7;
        float a0 = 0.f, a1 = 0.f;
        #pragma unroll 4
        for (int j = 0; j < NN; j++) {
            float v = __ldg(vp + (b * NN + j) * CC + c);
            a0 += edge[rr][j] * v;
            a1 += edge[rr + 2][j] * v;
        }
        nf[rr][CC + c] = a0;
        nf[rr + 2][CC + c] = a1;
    }
    __syncthreads();

    {
        float acc[4] = {0.f, 0.f, 0.f, 0.f};
        #pragma unroll 4
        for (int k = 0; k < 2 * CC; k++) {
            float w = __ldg(w1 + k * 2 * CC + tid);
            #pragma unroll
            for (int r = 0; r < 4; r++) acc[r] += nf[r][k] * w;
        }
        #pragma unroll
        for (int r = 0; r < 4; r++) hb[r][tid] = lrelu(acc[r] * BN_SCALE);
    }
    __syncthreads();

    {
        const int oc = tid & 127, rr = tid >> 7;
        float a0 = 0.f, a1 = 0.f;
        #pragma unroll 4
        for (int k = 0; k < 2 * CC; k++) {
            float w = __ldg(w2 + k * CC + oc);
            a0 += hb[rr][k] * w;
            a1 += hb[rr + 2][k] * w;
        }
        vp_out[(b * NN + it * 4 + rr) * CC + oc] = lrelu(a0 * BN_SCALE);
        vp_out[(b * NN + it * 4 + rr + 2) * CC + oc] = lrelu(a1 * BN_SCALE);
    }
}

// ---------------------------------------------------------------------------

extern "C" void kernel_launch(void* const* d_in, const int* in_sizes, int n_in,
                              void* d_out, int out_size)
{
    const float* vp   = (const float*)d_in[0];
    const float* ep0  = (const float*)d_in[1];
    const float* pw1  = (const float*)d_in[2];
    const float* pw2  = (const float*)d_in[3];
    const float* pw3  = (const float*)d_in[4];
    const float* pb3  = (const float*)d_in[5];
    const float* psw1 = (const float*)d_in[6];
    const float* psw2 = (const float*)d_in[7];
    const float* psw3 = (const float*)d_in[8];
    const float* psb3 = (const float*)d_in[9];
    const float* dw1  = (const float*)d_in[10];
    const float* dw2  = (const float*)d_in[11];
    const float* wq   = (const float*)d_in[12];
    const float* wk   = (const float*)d_in[13];
    float* out = (float*)d_out;

    const int mha_smem = (int)sizeof(MhaSmem);
    cudaFuncSetAttribute(psim_mma, cudaFuncAttributeMaxDynamicSharedMemorySize, SMEM_PS);
    cudaFuncSetAttribute(mha_kernel, cudaFuncAttributeMaxDynamicSharedMemorySize, mha_smem);

    float *ep, *epattn, *Q, *K, *vp1, *vp2, *w1P, *w2P;
    cudaGetSymbolAddress((void**)&ep, g_ep);
    cudaGetSymbolAddress((void**)&epattn, g_epattn);
    cudaGetSymbolAddress((void**)&Q, g_Q);
    cudaGetSymbolAddress((void**)&K, g_K);
    cudaGetSymbolAddress((void**)&vp1, g_vp1);
    cudaGetSymbolAddress((void**)&vp2, g_vp2);
    cudaGetSymbolAddress((void**)&w1P, g_w1P);
    cudaGetSymbolAddress((void**)&w2P, g_w2P);

    prep_weights<<<128, 256>>>(pw1, pw2, w1P, w2P);
    prep_weights<<<128, 256>>>(psw1, psw2, w1P + 32768, w2P + 32768);
    prep_weights<<<128, 256>>>(psw1 + CC * C2, psw2 + C2 * CC, w1P + 2 * 32768, w2P + 2 * 32768);

    dim3 grid(NN, BB);
    dim3 grid_d2p(NN / 4, BB);

    psim_mma<<<grid, 256, SMEM_PS>>>(vp, ep0, ep, w1P, w2P, pw3, pb3, 0);

    for (int g = 0; g < 2; g++) {
        const float* vpc = (g == 0) ? vp : vp1;
        float* vpn = (g == 0) ? vp1 : vp2;

        qk_kernel<<<BB * NN, 128>>>(vpc, wq + g * CC * CC, wk + g * CC * CC, Q, K);
        mha_kernel<<<grid, 128, mha_smem>>>(Q, K, ep, epattn);
        d2p_kernel<<<grid_d2p, 256>>>(epattn, vpc,
                                      dw1 + g * 2 * CC * 2 * CC,
                                      dw2 + g * 2 * CC * CC, vpn);

        const int kv = (g == 0) ? 115 : 102;
        float* epo = (g == 1) ? out : ep;
        psim_mma<<<grid, 256, SMEM_PS>>>(vpn, ep, epo,
                                         w1P + (g + 1) * 32768,
                                         w2P + (g + 1) * 32768,
                                         psw3 + g * CC,
                                         psb3 + g, kv);
    }
}

// round 7
// speedup vs baseline: 6.8345x; 1.8026x over previous
#include <cuda_runtime.h>
#include <math.h>
#include <stdint.h>

#define BB 8
#define NN 128
#define CC 128
#define C2 256
#define HH 4
#define DKK 32
#define BN_SCALE 0.9999950000374997f

__device__ float g_ep[BB*NN*NN];
__device__ float g_epattn[BB*NN*NN];
__device__ float g_Q[BB*NN*CC];
__device__ float g_K[BB*NN*CC];
__device__ float g_vp1[BB*NN*CC];
__device__ float g_vp2[BB*NN*CC];
__device__ uint4 g_w1P[3 * 4096];   // bf16 fragment-packed w1 per set
__device__ uint4 g_w2P[3 * 4096];   // bf16 fragment-packed w2 per set

__device__ __forceinline__ float lrelu(float x) { return x > 0.f ? x : 0.01f * x; }
__device__ __forceinline__ uint32_t pack_bf16(float lo, float hi) {
    uint32_t r; asm("cvt.rn.bf16x2.f32 %0, %1, %2;" : "=r"(r) : "f"(hi), "f"(lo)); return r;
}

__device__ __forceinline__ void mma_bf16(float* c, const uint4& a, uint32_t b0, uint32_t b1) {
    asm volatile(
        "mma.sync.aligned.m16n8k16.row.col.f32.bf16.bf16.f32 "
        "{%0,%1,%2,%3}, {%4,%5,%6,%7}, {%8,%9}, {%0,%1,%2,%3};"
        : "+f"(c[0]), "+f"(c[1]), "+f"(c[2]), "+f"(c[3])
        : "r"(a.x), "r"(a.y), "r"(a.z), "r"(a.w), "r"(b0), "r"(b1));
}

// ---------------- weight prep: bf16 B-fragment packing -----------------------
// w1P slot s = ((ch*2+np)*8+kt)*32+lane:
//   o0 = ch*32+np*16+(lane>>2), o1 = o0+8, k0 = kt*16+(lane&3)*2
//   .x={w1[k0][o0],w1[k0+1][o0]} .y={w1[k0+8][o0],w1[k0+9][o0]} .z/.w same with o1
// w2P slot s = ((kh*8+ntp)*8+ktl)*32+lane:
//   o0 = ntp*16+(lane>>2), o1 = o0+8, k0 = (kh*8+ktl)*16+(lane&3)*2
__global__ void prep_weights(const float* __restrict__ w1, const float* __restrict__ w2,
                             uint4* __restrict__ w1P, uint4* __restrict__ w2P)
{
    int idx = blockIdx.x * 256 + threadIdx.x;   // 0..4095
    {
        int lane = idx & 31, kt = (idx >> 5) & 7, np = (idx >> 8) & 1, ch = idx >> 9;
        int o0 = ch * 32 + np * 16 + (lane >> 2);
        int k0 = kt * 16 + (lane & 3) * 2;
        uint4 v;
        v.x = pack_bf16(w1[k0 * C2 + o0],       w1[(k0 + 1) * C2 + o0]);
        v.y = pack_bf16(w1[(k0 + 8) * C2 + o0], w1[(k0 + 9) * C2 + o0]);
        v.z = pack_bf16(w1[k0 * C2 + o0 + 8],       w1[(k0 + 1) * C2 + o0 + 8]);
        v.w = pack_bf16(w1[(k0 + 8) * C2 + o0 + 8], w1[(k0 + 9) * C2 + o0 + 8]);
        w1P[idx] = v;
    }
    {
        int lane = idx & 31, ktl = (idx >> 5) & 7, ntp = (idx >> 8) & 7, kh = idx >> 11;
        int o0 = ntp * 16 + (lane >> 2);
        int k0 = (kh * 8 + ktl) * 16 + (lane & 3) * 2;
        uint4 v;
        v.x = pack_bf16(w2[k0 * CC + o0],       w2[(k0 + 1) * CC + o0]);
        v.y = pack_bf16(w2[(k0 + 8) * CC + o0], w2[(k0 + 9) * CC + o0]);
        v.z = pack_bf16(w2[k0 * CC + o0 + 8],       w2[(k0 + 1) * CC + o0 + 8]);
        v.w = pack_bf16(w2[(k0 + 8) * CC + o0 + 8], w2[(k0 + 9) * CC + o0 + 8]);
        w2P[idx] = v;
    }
}

// ---------------- psim via bf16 mma.sync -------------------------------------
#define MS_SIM  0        // 32KB: sim A-frags [kt8][mt8][lane]16B; later w2 stage
#define MS_H1   32768    // 64KB: h1 A-frags [kt2 16][mt8][lane]16B
#define MS_WBUF 98304    // 8KB: w1 chunk [np2][kt8][lane]16B
#define MS_VPI  106496
#define MS_W3S  107008
#define MS_EPL  107520
#define MS_EROW 108032
#define MS_RED  108544
#define MS_L3   109056   // 256 floats
#define SMEM_PS 110080

__global__ void __launch_bounds__(256, 2)
psim_mma(const float* __restrict__ vp,
         const float* __restrict__ ep_in,
         float* __restrict__ ep_out,
         const uint4* __restrict__ w1P,
         const uint4* __restrict__ w2P,
         const float* __restrict__ w3,
         const float* __restrict__ b3,
         int kval)
{
    extern __shared__ char smem[];
    float* s_vpi  = (float*)(smem + MS_VPI);
    float* s_w3   = (float*)(smem + MS_W3S);
    float* s_epl  = (float*)(smem + MS_EPL);
    float* s_erow = (float*)(smem + MS_EROW);
    float* s_red  = (float*)(smem + MS_RED);
    float* s_l3   = (float*)(smem + MS_L3);
    const int i = blockIdx.x, b = blockIdx.y;
    const int tid = threadIdx.x, w = tid >> 5, lane = tid & 31;
    const int wm = w & 3, wn = w >> 2;
    const int row = b * NN + i;

    if (tid < 128) {
        s_vpi[tid] = vp[row * CC + tid];
        s_w3[tid]  = w3[tid];
        float v = ep_in[row * NN + tid];
        s_epl[tid] = (tid == i) ? 0.f : v;
    }
    __syncthreads();

    // build sim A-frags (bf16): element (j,c) -> (vpi[c]-vp[j,c])^2
    for (int q = tid; q < 4096; q += 256) {
        int j = q >> 5, c0 = (q & 31) << 2;
        const float4 vj = *(const float4*)(vp + (b * NN + j) * CC + c0);
        const float4 vi = *(const float4*)(s_vpi + c0);
        float d0 = vi.x - vj.x, d1 = vi.y - vj.y, d2 = vi.z - vj.z, d3 = vi.w - vj.w;
        uint32_t p01 = pack_bf16(d0 * d0, d1 * d1);
        uint32_t p23 = pack_bf16(d2 * d2, d3 * d3);
        int kt = c0 >> 4, mt = j >> 4;
        int reg = ((j >> 3) & 1) + (((c0 & 15) >> 3) << 1);
        uint32_t addr = (uint32_t)(((kt * 8 + mt) * 32 + (j & 7) * 4 + ((c0 & 7) >> 1)) * 16 + reg * 4);
        *(uint32_t*)(smem + MS_SIM + addr)      = p01;
        *(uint32_t*)(smem + MS_SIM + addr + 16) = p23;
    }
    __syncthreads();

    // A fragments resident (rows wm*32..wm*32+31): 16 uint4
    uint4 Areg[8][2];
    #pragma unroll
    for (int kt = 0; kt < 8; kt++)
        #pragma unroll
        for (int m = 0; m < 2; m++)
            Areg[kt][m] = *(const uint4*)(smem + MS_SIM + ((kt * 8 + wm * 2 + m) * 32 + lane) * 16);

    // ---- GEMM1: D1[128,256] = sim @ w1^T, 8 chunks of 32 o ----
    uint4 pf0 = __ldg(w1P + tid), pf1 = __ldg(w1P + 256 + tid);
    for (int ch = 0; ch < 8; ch++) {
        *(uint4*)(smem + MS_WBUF + tid * 16) = pf0;
        *(uint4*)(smem + MS_WBUF + (256 + tid) * 16) = pf1;
        __syncthreads();
        if (ch < 7) {
            pf0 = __ldg(w1P + (ch + 1) * 512 + tid);
            pf1 = __ldg(w1P + (ch + 1) * 512 + 256 + tid);
        }
        float acc[2][2][4];
        #pragma unroll
        for (int m = 0; m < 2; m++)
            #pragma unroll
            for (int n = 0; n < 2; n++)
                #pragma unroll
                for (int t = 0; t < 4; t++) acc[m][n][t] = 0.f;
        #pragma unroll
        for (int kt = 0; kt < 8; kt++) {
            uint4 W = *(const uint4*)(smem + MS_WBUF + ((wn * 8 + kt) * 32 + lane) * 16);
            mma_bf16(acc[0][0], Areg[kt][0], W.x, W.y);
            mma_bf16(acc[0][1], Areg[kt][0], W.z, W.w);
            mma_bf16(acc[1][0], Areg[kt][1], W.x, W.y);
            mma_bf16(acc[1][1], Areg[kt][1], W.z, W.w);
        }
        // epilogue -> h1 bf16 A-frags
        #pragma unroll
        for (int m = 0; m < 2; m++)
            #pragma unroll
            for (int ntl = 0; ntl < 2; ntl++) {
                uint2 st;
                st.x = pack_bf16(lrelu(acc[m][ntl][0] * BN_SCALE), lrelu(acc[m][ntl][1] * BN_SCALE));
                st.y = pack_bf16(lrelu(acc[m][ntl][2] * BN_SCALE), lrelu(acc[m][ntl][3] * BN_SCALE));
                uint32_t addr = (uint32_t)((((ch * 2 + wn) * 8 + wm * 2 + m) * 32 + lane) * 16 + ntl * 8);
                *(uint2*)(smem + MS_H1 + addr) = st;
            }
        __syncthreads();
    }

    // ---- GEMM2: D2[128,128] = h1 @ w2^T; B staged in 2 k-halves (32 KB each) ----
    float acc2[2][8][4];
    #pragma unroll
    for (int m = 0; m < 2; m++)
        #pragma unroll
        for (int n = 0; n < 8; n++)
            #pragma unroll
            for (int t = 0; t < 4; t++) acc2[m][n][t] = 0.f;

    for (int kh = 0; kh < 2; kh++) {
        uint4 pf2[4];
        #pragma unroll
        for (int t = 0; t < 4; t++) pf2[t] = __ldg(w2P + kh * 2048 + tid + t * 256);
        __syncthreads();   // prior readers of MS_SIM done
        #pragma unroll
        for (int t = 0; t < 4; t++)
            *(uint4*)(smem + MS_SIM + (tid + t * 256) * 16) = pf2[t];
        #pragma unroll
        for (int t = 0; t < 4; t++) pf2[t] = __ldg(w2P + kh * 2048 + 1024 + tid + t * 256);
        #pragma unroll
        for (int t = 0; t < 4; t++)
            *(uint4*)(smem + MS_SIM + (1024 + tid + t * 256) * 16) = pf2[t];
        __syncthreads();
        #pragma unroll 2
        for (int ktl = 0; ktl < 8; ktl++) {
            int kt2 = kh * 8 + ktl;
            uint4 A0 = *(const uint4*)(smem + MS_H1 + ((kt2 * 8 + wm * 2) * 32 + lane) * 16);
            uint4 A1 = *(const uint4*)(smem + MS_H1 + ((kt2 * 8 + wm * 2 + 1) * 32 + lane) * 16);
            #pragma unroll
            for (int pp = 0; pp < 4; pp++) {
                uint4 W = *(const uint4*)(smem + MS_SIM + (((wn * 4 + pp) * 8 + ktl) * 32 + lane) * 16);
                int q = pp * 2;
                mma_bf16(acc2[0][q],     A0, W.x, W.y);
                mma_bf16(acc2[0][q + 1], A0, W.z, W.w);
                mma_bf16(acc2[1][q],     A1, W.x, W.y);
                mma_bf16(acc2[1][q + 1], A1, W.z, W.w);
            }
        }
    }

    // ---- layer3 partials + reduce ----
    const float b3v = b3[0];
    float pr[4] = {0.f, 0.f, 0.f, 0.f};
    #pragma unroll
    for (int m = 0; m < 2; m++)
        #pragma unroll
        for (int q = 0; q < 8; q++) {
            int o = wn * 64 + q * 8 + (lane & 3) * 2;
            float wa = s_w3[o], wb = s_w3[o + 1];
            pr[m * 2]     += lrelu(acc2[m][q][0] * BN_SCALE) * wa + lrelu(acc2[m][q][1] * BN_SCALE) * wb;
            pr[m * 2 + 1] += lrelu(acc2[m][q][2] * BN_SCALE) * wa + lrelu(acc2[m][q][3] * BN_SCALE) * wb;
        }
    #pragma unroll
    for (int t = 0; t < 4; t++) {
        pr[t] += __shfl_xor_sync(0xffffffffu, pr[t], 1);
        pr[t] += __shfl_xor_sync(0xffffffffu, pr[t], 2);
    }
    if ((lane & 3) == 0) {
        int g = lane >> 2;
        s_l3[wn * 128 + wm * 32 + g]      = pr[0];
        s_l3[wn * 128 + wm * 32 + g + 8]  = pr[1];
        s_l3[wn * 128 + wm * 32 + g + 16] = pr[2];
        s_l3[wn * 128 + wm * 32 + g + 24] = pr[3];
    }
    __syncthreads();
    if (tid < 128) {
        float e = s_l3[tid] + s_l3[128 + tid];
        s_erow[tid] = 1.0f / (1.0f + expf(-(e + b3v)));
    }
    __syncthreads();

    // ---- row postprocess ----
    if (tid < 128) s_red[tid] = s_epl[tid];
    __syncthreads();
    for (int st = 64; st > 0; st >>= 1) { if (tid < st) s_red[tid] += s_red[tid + st]; __syncthreads(); }
    const float epsum = s_red[0];
    __syncthreads();

    if (tid < 128) s_erow[tid] *= s_epl[tid];
    __syncthreads();

    if (kval > 0 && kval < NN) {
        int cnt = 0;
        if (tid < 128) {
            float mine = s_erow[tid];
            for (int jj = 0; jj < NN; jj++) {
                float v = s_erow[jj];
                cnt += (v > mine) || (v == mine && jj < tid);
            }
        }
        __syncthreads();
        if (tid < 128 && cnt >= kval) s_erow[tid] = 0.f;
        __syncthreads();
    }

    if (tid < 128) s_red[tid] = fabsf(s_erow[tid]);
    __syncthreads();
    for (int st = 64; st > 0; st >>= 1) { if (tid < st) s_red[tid] += s_red[tid + st]; __syncthreads(); }
    const float l1 = s_red[0];
    __syncthreads();

    const float scale = epsum / fmaxf(l1, 1e-12f);
    if (tid < 128)
        s_erow[tid] = s_erow[tid] * scale + ((tid == i) ? 1.0f : 0.0f) + 1e-6f;
    __syncthreads();

    if (tid < 128) s_red[tid] = s_erow[tid];
    __syncthreads();
    for (int st = 64; st > 0; st >>= 1) { if (tid < st) s_red[tid] += s_red[tid + st]; __syncthreads(); }
    const float rsum = s_red[0];
    __syncthreads();

    if (tid < 128) ep_out[row * NN + tid] = s_erow[tid] / rsum;
}

// ---------------- Q/K projection -------------------------------------------
__global__ void qk_kernel(const float* __restrict__ vp,
                          const float* __restrict__ wq,
                          const float* __restrict__ wk,
                          float* __restrict__ Q,
                          float* __restrict__ K)
{
    __shared__ float vr[CC];
    const int r = blockIdx.x;
    const int tid = threadIdx.x;  // 128
    vr[tid] = vp[r * CC + tid];
    __syncthreads();
    float aq = 0.f, ak = 0.f;
    #pragma unroll 4
    for (int c = 0; c < CC; c++) {
        float v = vr[c];
        aq += v * __ldg(wq + c * CC + tid);
        ak += v * __ldg(wk + c * CC + tid);
    }
    Q[r * CC + tid] = aq;
    K[r * CC + tid] = ak;
}

// ---------------- MHA + ep*attn --------------------------------------------
struct MhaSmem {
    float q[CC];
    float red[NN];
    float Ks[NN * (CC + 1)];
};

__global__ void mha_kernel(const float* __restrict__ Q,
                           const float* __restrict__ K,
                           const float* __restrict__ ep,
                           float* __restrict__ epattn)
{
    extern __shared__ float smem_raw[];
    MhaSmem& s = *reinterpret_cast<MhaSmem*>(smem_raw);
    const int qi = blockIdx.x;
    const int b = blockIdx.y;
    const int tid = threadIdx.x;  // 128
    const int row = b * NN + qi;

    s.q[tid] = Q[row * CC + tid];
    for (int idx = tid; idx < NN * CC; idx += 128) {
        int j = idx >> 7, c = idx & 127;
        s.Ks[j * (CC + 1) + c] = K[(b * NN + j) * CC + c];
    }
    __syncthreads();

    const float inv = 0.17677669529663687f;
    float acc = 0.f;
    for (int h = 0; h < HH; h++) {
        float sc = 0.f;
        const float* kr = s.Ks + tid * (CC + 1) + h * DKK;
        const float* qr = s.q + h * DKK;
        #pragma unroll
        for (int d = 0; d < DKK; d++) sc += qr[d] * kr[d];
        sc *= inv;

        s.red[tid] = sc;
        __syncthreads();
        for (int st = 64; st > 0; st >>= 1) { if (tid < st) s.red[tid] = fmaxf(s.red[tid], s.red[tid + st]); __syncthreads(); }
        float mx = s.red[0];
        __syncthreads();
        float ex = expf(sc - mx);
        s.red[tid] = ex;
        __syncthreads();
        for (int st = 64; st > 0; st >>= 1) { if (tid < st) s.red[tid] += s.red[tid + st]; __syncthreads(); }
        float sm = s.red[0];
        __syncthreads();
        acc += ex / sm;
    }
    epattn[row * NN + tid] = ep[row * NN + tid] * (acc * 0.25f);
}

// ---------------- D2P: 4 rows/block, 256 threads ----------------------------
__global__ void __launch_bounds__(256)
d2p_kernel(const float* __restrict__ epattn,
           const float* __restrict__ vp,
           const float* __restrict__ w1,
           const float* __restrict__ w2,
           float* __restrict__ vp_out)
{
    __shared__ float edge[4][NN];
    __shared__ float nf[4][2 * CC];
    __shared__ float hb[4][2 * CC];
    const int it = blockIdx.x;
    const int b = blockIdx.y;
    const int tid = threadIdx.x;
    const int wid = tid >> 5, lane = tid & 31;

    if (wid < 4) {
        const int i = it * 4 + wid;
        const int row = b * NN + i;
        float e[4];
        float ssum = 0.f;
        #pragma unroll
        for (int q = 0; q < 4; q++) {
            int j = lane + 32 * q;
            float v = epattn[row * NN + j];
            if (j == i) v = 0.f;
            e[q] = v;
            ssum += fabsf(v);
        }
        #pragma unroll
        for (int st = 16; st > 0; st >>= 1) ssum += __shfl_xor_sync(0xffffffffu, ssum, st);
        float inv = 1.0f / fmaxf(ssum, 1e-12f);
        #pragma unroll
        for (int q = 0; q < 4; q++) {
            int j = lane + 32 * q;
            edge[wid][j] = e[q] * inv;
            nf[wid][j] = vp[row * CC + j];
        }
    }
    __syncthreads();

    {
        const int c = tid & 127, rr = tid >> 7;
        float a0 = 0.f, a1 = 0.f;
        #pragma unroll 4
        for (int j = 0; j < NN; j++) {
            float v = __ldg(vp + (b * NN + j) * CC + c);
            a0 += edge[rr][j] * v;
            a1 += edge[rr + 2][j] * v;
        }
        nf[rr][CC + c] = a0;
        nf[rr + 2][CC + c] = a1;
    }
    __syncthreads();

    {
        float acc[4] = {0.f, 0.f, 0.f, 0.f};
        #pragma unroll 4
        for (int k = 0; k < 2 * CC; k++) {
            float w = __ldg(w1 + k * 2 * CC + tid);
            #pragma unroll
            for (int r = 0; r < 4; r++) acc[r] += nf[r][k] * w;
        }
        #pragma unroll
        for (int r = 0; r < 4; r++) hb[r][tid] = lrelu(acc[r] * BN_SCALE);
    }
    __syncthreads();

    {
        const int oc = tid & 127, rr = tid >> 7;
        float a0 = 0.f, a1 = 0.f;
        #pragma unroll 4
        for (int k = 0; k < 2 * CC; k++) {
            float w = __ldg(w2 + k * CC + oc);
            a0 += hb[rr][k] * w;
            a1 += hb[rr + 2][k] * w;
        }
        vp_out[(b * NN + it * 4 + rr) * CC + oc] = lrelu(a0 * BN_SCALE);
        vp_out[(b * NN + it * 4 + rr + 2) * CC + oc] = lrelu(a1 * BN_SCALE);
    }
}

// ---------------------------------------------------------------------------

extern "C" void kernel_launch(void* const* d_in, const int* in_sizes, int n_in,
                              void* d_out, int out_size)
{
    const float* vp   = (const float*)d_in[0];
    const float* ep0  = (const float*)d_in[1];
    const float* pw1  = (const float*)d_in[2];
    const float* pw2  = (const float*)d_in[3];
    const float* pw3  = (const float*)d_in[4];
    const float* pb3  = (const float*)d_in[5];
    const float* psw1 = (const float*)d_in[6];
    const float* psw2 = (const float*)d_in[7];
    const float* psw3 = (const float*)d_in[8];
    const float* psb3 = (const float*)d_in[9];
    const float* dw1  = (const float*)d_in[10];
    const float* dw2  = (const float*)d_in[11];
    const float* wq   = (const float*)d_in[12];
    const float* wk   = (const float*)d_in[13];
    float* out = (float*)d_out;

    const int mha_smem = (int)sizeof(MhaSmem);
    cudaFuncSetAttribute(psim_mma, cudaFuncAttributeMaxDynamicSharedMemorySize, SMEM_PS);
    cudaFuncSetAttribute(mha_kernel, cudaFuncAttributeMaxDynamicSharedMemorySize, mha_smem);

    float *ep, *epattn, *Q, *K, *vp1, *vp2;
    uint4 *w1P, *w2P;
    cudaGetSymbolAddress((void**)&ep, g_ep);
    cudaGetSymbolAddress((void**)&epattn, g_epattn);
    cudaGetSymbolAddress((void**)&Q, g_Q);
    cudaGetSymbolAddress((void**)&K, g_K);
    cudaGetSymbolAddress((void**)&vp1, g_vp1);
    cudaGetSymbolAddress((void**)&vp2, g_vp2);
    cudaGetSymbolAddress((void**)&w1P, g_w1P);
    cudaGetSymbolAddress((void**)&w2P, g_w2P);

    prep_weights<<<16, 256>>>(pw1, pw2, w1P, w2P);
    prep_weights<<<16, 256>>>(psw1, psw2, w1P + 4096, w2P + 4096);
    prep_weights<<<16, 256>>>(psw1 + CC * C2, psw2 + C2 * CC, w1P + 2 * 4096, w2P + 2 * 4096);

    dim3 grid(NN, BB);
    dim3 grid_d2p(NN / 4, BB);

    psim_mma<<<grid, 256, SMEM_PS>>>(vp, ep0, ep, w1P, w2P, pw3, pb3, 0);

    for (int g = 0; g < 2; g++) {
        const float* vpc = (g == 0) ? vp : vp1;
        float* vpn = (g == 0) ? vp1 : vp2;

        qk_kernel<<<BB * NN, 128>>>(vpc, wq + g * CC * CC, wk + g * CC * CC, Q, K);
        mha_kernel<<<grid, 128, mha_smem>>>(Q, K, ep, epattn);
        d2p_kernel<<<grid_d2p, 256>>>(epattn, vpc,
                                      dw1 + g * 2 * CC * 2 * CC,
                                      dw2 + g * 2 * CC * CC, vpn);

        const int kv = (g == 0) ? 115 : 102;
        float* epo = (g == 1) ? out : ep;
        psim_mma<<<grid, 256, SMEM_PS>>>(vpn, ep, epo,
                                         w1P + (g + 1) * 4096,
                                         w2P + (g + 1) * 4096,
                                         psw3 + g * CC,
                                         psb3 + g, kv);
    }
}